// round 11
// baseline (speedup 1.0000x reference)
#include <cuda_runtime.h>
#include <cuda_fp16.h>
#include <cstdint>

typedef unsigned long long ull;

// Problem constants
#define BB 4
#define NN 2048
#define II 32
#define HH 64
#define OO 32
#define EE 2
#define HD 2
#define EH 4              // E*HD
#define CC 16             // EH*B combos
#define D1 256            // H*HD*E
#define BNN 16777216      // B*N*N
#define SLAB (NN*NN/2)    // half2 per (e,b) slab

// ---------------- scratch (device globals; no allocation) ----------------
__device__ __half2 g_edgeH2[BNN];            // [e][b][i][k] fp16, 67MB
__device__ float g_state0[BB * NN * HH];
__device__ float g_state1[BB * NN * D1];
__device__ float g_Wh [CC * NN * HH];
__device__ __half2 g_WhnT[CC * 64 * 1024];   // [c][d][k/2]  fp16 normalized transposed
__device__ float g_a1[CC * NN];
__device__ float g_a2[CC * NN];
__device__ float g_s [CC * NN];
__device__ float g_spart[8 * CC * NN];
__device__ float g_msg1[CC * NN * HH];
__device__ float g_partial[BB * 16 * HH];

// ---------------- f32x2 packed helpers (Blackwell FFMA2) ----------------
__device__ __forceinline__ ull pk2(float x) {
    ull r;
    asm("mov.b64 %0, {%1, %1};" : "=l"(r) : "f"(x));
    return r;
}
__device__ __forceinline__ void fma2(ull& d, ull a, ull b) {
    asm("fma.rn.f32x2 %0, %1, %2, %0;" : "+l"(d) : "l"(a), "l"(b));
}
__device__ __forceinline__ void upk2(ull v, float& lo, float& hi) {
    asm("mov.b64 {%0, %1}, %2;" : "=f"(lo), "=f"(hi) : "l"(v));
}

// ---------------- HMMA helper: m16n8k16 fp16 -> fp32 ----------------
__device__ __forceinline__ void mma16816(float* d,
                                         uint32_t a0, uint32_t a1,
                                         uint32_t a2, uint32_t a3,
                                         uint32_t b0, uint32_t b1) {
    asm volatile(
        "mma.sync.aligned.m16n8k16.row.col.f32.f16.f16.f32 "
        "{%0,%1,%2,%3}, {%4,%5,%6,%7}, {%8,%9}, {%0,%1,%2,%3};"
        : "+f"(d[0]), "+f"(d[1]), "+f"(d[2]), "+f"(d[3])
        : "r"(a0), "r"(a1), "r"(a2), "r"(a3), "r"(b0), "r"(b1));
}

// exp of a k-pair packed to half2 (bit pattern as u32 for the MMA frag)
__device__ __forceinline__ uint32_t expp(float a1v, float2 a2v, __half2 ev) {
    float2 e = __half22float2(ev);
    float l0 = a1v + a2v.x; l0 = l0 > 0.f ? l0 : 0.2f * l0;
    float l1 = a1v + a2v.y; l1 = l1 > 0.f ? l1 : 0.2f * l1;
    __half2 h = __floats2half2_rn(__expf(l0 + e.x), __expf(l1 + e.y));
    return *reinterpret_cast<uint32_t*>(&h);
}
__device__ __forceinline__ uint32_t h2u(__half2 h) {
    return *reinterpret_cast<uint32_t*>(&h);
}

// ---------------- kernels ----------------

// split interleaved fp32 edges (B,N,N,E) -> two contiguous fp16 slabs
__global__ void k_split_edges(const float* __restrict__ edges) {
    size_t t = (size_t)blockIdx.x * blockDim.x + threadIdx.x;  // over BNN/2 float4s
    float4 v = ((const float4*)edges)[t];
    g_edgeH2[t]           = __floats2half2_rn(v.x, v.z);   // e=0
    g_edgeH2[BNN / 2 + t] = __floats2half2_rn(v.y, v.w);   // e=1
}

// state0 = nodes @ W_emb + b_emb
__global__ void k_embed(const float* __restrict__ nodes,
                        const float* __restrict__ Wemb,
                        const float* __restrict__ bemb) {
    __shared__ float sW[II * HH];
    int tid = threadIdx.x;
    for (int i = tid; i < II * HH; i += 256) sW[i] = Wemb[i];
    __syncthreads();
    int row = blockIdx.x * 4 + (tid >> 6);
    int h = tid & 63;
    const float* nr = nodes + (size_t)row * II;
    float acc = bemb[h];
#pragma unroll
    for (int d = 0; d < II; d++) acc += __ldg(&nr[d]) * sW[d * HH + h];
    g_state0[(size_t)row * HH + h] = acc;
}

// Wh[eh,b,n,:] = state @ Wf[eh]   64x64 tile, FFMA2 micro-kernel
template <int DIN>
__global__ void __launch_bounds__(128) k_wh(const float* __restrict__ Wf) {
    __shared__ float sS[64][66];
    __shared__ __align__(16) float sW[64][68];
    const float* src = (DIN == 64) ? g_state0 : g_state1;
    int tid = threadIdx.x;
    int n0 = blockIdx.x * 64;
    int b = blockIdx.y;
    int eh = blockIdx.z;
    const float* Wfe = Wf + (size_t)eh * DIN * 64;
    const float* S = src + ((size_t)b * NN + n0) * DIN;
    int ti = tid >> 3, td = tid & 7;
    int ry = tid >> 1, xs = (tid & 1) * 32;
    ull acc[16];
#pragma unroll
    for (int r = 0; r < 16; r++) acc[r] = 0ULL;

    for (int d0 = 0; d0 < DIN; d0 += 64) {
        __syncthreads();
#pragma unroll
        for (int j = 0; j < 8; j++) {
            float4 v = *(const float4*)&S[(size_t)ry * DIN + d0 + xs + 4 * j];
            sS[ry][xs + 4 * j + 0] = v.x;
            sS[ry][xs + 4 * j + 1] = v.y;
            sS[ry][xs + 4 * j + 2] = v.z;
            sS[ry][xs + 4 * j + 3] = v.w;
        }
#pragma unroll
        for (int j = 0; j < 8; j++)
            *(float4*)&sW[ry][xs + 4 * j] =
                *(const float4*)&Wfe[(size_t)(d0 + ry) * 64 + xs + 4 * j];
        __syncthreads();
#pragma unroll 8
        for (int d = 0; d < 64; d++) {
            const ull* wp = (const ull*)&sW[d][8 * td];
            ull w0 = wp[0], w1 = wp[1], w2v = wp[2], w3 = wp[3];
#pragma unroll
            for (int r = 0; r < 4; r++) {
                ull s = pk2(sS[4 * ti + r][d]);
                fma2(acc[4 * r + 0], s, w0);
                fma2(acc[4 * r + 1], s, w1);
                fma2(acc[4 * r + 2], s, w2v);
                fma2(acc[4 * r + 3], s, w3);
            }
        }
    }
    size_t base = (size_t)(eh * BB + b) * NN + n0;
#pragma unroll
    for (int r = 0; r < 4; r++) {
        float o[8];
        upk2(acc[4 * r + 0], o[0], o[1]);
        upk2(acc[4 * r + 1], o[2], o[3]);
        upk2(acc[4 * r + 2], o[4], o[5]);
        upk2(acc[4 * r + 3], o[6], o[7]);
        float* dst = &g_Wh[(base + 4 * ti + r) * 64 + 8 * td];
        *(float4*)dst = make_float4(o[0], o[1], o[2], o[3]);
        *(float4*)(dst + 4) = make_float4(o[4], o[5], o[6], o[7]);
    }
}

// a1 = Wh . w1 + b1 ; a2 = Wh . w2 + b2
__global__ void k_a12(const float* __restrict__ w1, const float* __restrict__ b1,
                      const float* __restrict__ w2, const float* __restrict__ b2) {
    int warp = (blockIdx.x * blockDim.x + threadIdx.x) >> 5;
    int lane = threadIdx.x & 31;
    int c = warp >> 11;
    int eh = c >> 2;
    const float* wh = g_Wh + (size_t)warp * 64;
    float x0 = wh[lane], x1 = wh[lane + 32];
    float d1 = x0 * w1[eh * 64 + lane] + x1 * w1[eh * 64 + lane + 32];
    float d2 = x0 * w2[eh * 64 + lane] + x1 * w2[eh * 64 + lane + 32];
#pragma unroll
    for (int o = 16; o; o >>= 1) {
        d1 += __shfl_down_sync(0xffffffffu, d1, o);
        d2 += __shfl_down_sync(0xffffffffu, d2, o);
    }
    if (lane == 0) {
        g_a1[warp] = d1 + b1[eh];
        g_a2[warp] = d2 + b2[eh];
    }
}

// partial s[k] over a 256-row i-chunk; grid (ktile=4, ichunk=8, c=16)
__global__ void __launch_bounds__(256) k_stats() {
    __shared__ float sA1[256];
    int c = blockIdx.z;
    int e = c >> 3, b = c & 3;
    int tid = threadIdx.x;
    int kbase = blockIdx.x * 512;
    int i0 = blockIdx.y * 256;
    sA1[tid] = g_a1[c * NN + i0 + tid];
    __syncthreads();
    int k = kbase + 2 * tid;
    float a20 = g_a2[c * NN + k], a21 = g_a2[c * NN + k + 1];
    const __half2* eg = g_edgeH2 + (size_t)(e * BB + b) * SLAB +
                        (size_t)i0 * (NN / 2) + (kbase >> 1) + tid;
    float s0 = 0.f, s1 = 0.f;
#pragma unroll 8
    for (int i = 0; i < 256; i++) {
        float2 ev = __half22float2(eg[(size_t)i * (NN / 2)]);
        float v = sA1[i];
        float l0 = v + a20; l0 = l0 > 0.f ? l0 : 0.2f * l0;
        float l1 = v + a21; l1 = l1 > 0.f ? l1 : 0.2f * l1;
        s0 += __expf(l0 + ev.x);
        s1 += __expf(l1 + ev.y);
    }
    float2* sp = (float2*)(g_spart + ((size_t)blockIdx.y * CC + c) * NN);
    sp[(kbase >> 1) + tid] = make_float2(s0, s1);
}

// reduce 8 partials -> g_s
__global__ void k_sred() {
    int idx = blockIdx.x * 256 + threadIdx.x;
    float s = 0.f;
#pragma unroll
    for (int ic = 0; ic < 8; ic++) s += g_spart[(size_t)ic * CC * NN + idx];
    g_s[idx] = s;
}

// WhnT[c][d][k] = (Wh[c][k][d] / s[c][k]) as fp16, transposed
__global__ void __launch_bounds__(256) k_whnT() {
    __shared__ float tl[64][65];
    int c = blockIdx.y;
    int k0 = blockIdx.x * 64;
    int tid = threadIdx.x;
    int ky = tid >> 6, d = tid & 63;
#pragma unroll
    for (int p = 0; p < 16; p++)
        tl[4 * p + ky][d] = g_Wh[((size_t)c * NN + k0 + 4 * p + ky) * 64 + d];
    __syncthreads();
    int lam = tid & 31, dw = tid >> 5;
    float2 s2 = *(const float2*)&g_s[c * NN + k0 + 2 * lam];
    float rx = __fdividef(1.f, s2.x), ry = __fdividef(1.f, s2.y);
#pragma unroll
    for (int q = 0; q < 8; q++) {
        int dd = dw * 8 + q;
        g_WhnT[(size_t)(c * 64 + dd) * 1024 + (k0 >> 1) + lam] =
            __floats2half2_rn(tl[2 * lam][dd] * rx, tl[2 * lam + 1][dd] * ry);
    }
}

// msg via HMMA m16n8k16: D[128 i, 64 d] = sum_k exp(...)[i,k] * WhnT[d,k]
// No shared memory: A fragments computed in registers, B loaded straight
// from global (fragment layouts match the half2 storage exactly).
template <int LAYER>
__global__ void __launch_bounds__(256) k_msg_mma(const float* __restrict__ bias) {
    int tid = threadIdx.x;
    int w = tid >> 5, lane = tid & 31;
    int grp = lane >> 2, qd = lane & 3;
    int c = blockIdx.y;
    int eh = c >> 2, b = c & 3;
    int e = eh >> 1, h = eh & 1;
    int i0 = blockIdx.x * 128;
    int iw = i0 + 16 * w;

    const __half2* eslab = g_edgeH2 + (size_t)(e * BB + b) * SLAB;
    const __half2* wT = g_WhnT + (size_t)c * 64 * 1024;
    const float* a2p = g_a2 + c * NN;

    float a1lo = g_a1[c * NN + iw + grp];
    float a1hi = g_a1[c * NN + iw + grp + 8];

    const __half2* erow_lo = eslab + (size_t)(iw + grp) * (NN / 2);
    const __half2* erow_hi = erow_lo + (size_t)8 * (NN / 2);

    float acc[8][4];
#pragma unroll
    for (int nt = 0; nt < 8; nt++)
#pragma unroll
        for (int j = 0; j < 4; j++) acc[nt][j] = 0.f;

    // edge double-buffer
    __half2 e0 = erow_lo[qd], e1 = erow_lo[qd + 4];
    __half2 e2 = erow_hi[qd], e3 = erow_hi[qd + 4];

#pragma unroll 2
    for (int t = 0; t < 128; t++) {
        int kh = 8 * t;
        __half2 c0 = e0, c1 = e1, c2 = e2, c3 = e3;
        if (t < 127) {
            e0 = erow_lo[kh + 8 + qd]; e1 = erow_lo[kh + 8 + qd + 4];
            e2 = erow_hi[kh + 8 + qd]; e3 = erow_hi[kh + 8 + qd + 4];
        }
        float2 a2lo = *(const float2*)&a2p[16 * t + 2 * qd];
        float2 a2hi = *(const float2*)&a2p[16 * t + 2 * qd + 8];

        uint32_t A0 = expp(a1lo, a2lo, c0);   // rows 0-7,  k 0-7
        uint32_t A1 = expp(a1hi, a2lo, c2);   // rows 8-15, k 0-7
        uint32_t A2 = expp(a1lo, a2hi, c1);   // rows 0-7,  k 8-15
        uint32_t A3 = expp(a1hi, a2hi, c3);   // rows 8-15, k 8-15

#pragma unroll
        for (int nt = 0; nt < 8; nt++) {
            const __half2* bp = wT + (size_t)(8 * nt + grp) * 1024 + kh + qd;
            uint32_t B0 = h2u(bp[0]);
            uint32_t B1 = h2u(bp[4]);
            mma16816(acc[nt], A0, A1, A2, A3, B0, B1);
        }
    }

    // store: c0,c1 -> (row grp, cols 2qd,2qd+1); c2,c3 -> row grp+8
    int gi_lo = iw + grp, gi_hi = iw + grp + 8;
#pragma unroll
    for (int nt = 0; nt < 8; nt++) {
        int col = 8 * nt + 2 * qd;
        float bx = bias[h * 64 + col], by = bias[h * 64 + col + 1];
        float2 vlo = make_float2(acc[nt][0] + bx, acc[nt][1] + by);
        float2 vhi = make_float2(acc[nt][2] + bx, acc[nt][3] + by);
        if (LAYER == 0) {
            *(float2*)&g_state1[((size_t)b * NN + gi_lo) * D1 + eh * 64 + col] = vlo;
            *(float2*)&g_state1[((size_t)b * NN + gi_hi) * D1 + eh * 64 + col] = vhi;
        } else {
            *(float2*)&g_msg1[((size_t)c * NN + gi_lo) * 64 + col] = vlo;
            *(float2*)&g_msg1[((size_t)c * NN + gi_hi) * 64 + col] = vhi;
        }
    }
}

// partial[b,chunk,h] = sum over eh and 128 n-rows of elu(msg1)
__global__ void k_reduce1() {
    int b = blockIdx.y, ch = blockIdx.x;
    int n0 = ch * 128;
    int h = threadIdx.x & 63, sub = threadIdx.x >> 6;
    float s = 0.f;
#pragma unroll
    for (int eh = 0; eh < EH; eh++) {
        const float* m = g_msg1 + ((size_t)(eh * BB + b) * NN + n0) * 64;
        for (int n = sub; n < 128; n += 4) {
            float x = m[(size_t)n * 64 + h];
            s += x > 0.f ? x : expm1f(x);
        }
    }
    __shared__ float red[256];
    red[threadIdx.x] = s;
    __syncthreads();
    if (threadIdx.x < 64)
        g_partial[(b * 16 + ch) * 64 + threadIdx.x] =
            red[threadIdx.x] + red[64 + threadIdx.x] +
            red[128 + threadIdx.x] + red[192 + threadIdx.x];
}

__global__ void k_out(const float* __restrict__ Wout,
                      const float* __restrict__ bout,
                      float* __restrict__ out) {
    __shared__ float v[BB * 64];
    int t = threadIdx.x;
    {
        int b = t >> 6, h = t & 63;
        float s = 0.f;
#pragma unroll
        for (int p = 0; p < 16; p++) s += g_partial[(b * 16 + p) * 64 + h];
        v[t] = s;
    }
    __syncthreads();
    if (t < 128) {
        int b = t >> 5, o = t & 31;
        float s = 0.f;
#pragma unroll
        for (int hh = 0; hh < 64; hh++) s += v[b * 64 + hh] * Wout[hh * OO + o];
        out[b * OO + o] = s * (1.f / 8192.f) + bout[o];
    }
}

// ---------------- launcher ----------------
extern "C" void kernel_launch(void* const* d_in, const int* in_sizes, int n_in,
                              void* d_out, int out_size) {
    const float* nodes = (const float*)d_in[0];
    const float* edges = (const float*)d_in[1];
    const float* W_emb = (const float*)d_in[2];
    const float* b_emb = (const float*)d_in[3];
    const float* Wf0   = (const float*)d_in[4];
    const float* w1_0  = (const float*)d_in[5];
    const float* b1_0  = (const float*)d_in[6];
    const float* w2_0  = (const float*)d_in[7];
    const float* b2_0  = (const float*)d_in[8];
    const float* bias0 = (const float*)d_in[9];
    const float* Wf1   = (const float*)d_in[10];
    const float* w1_1  = (const float*)d_in[11];
    const float* b1_1  = (const float*)d_in[12];
    const float* w2_1  = (const float*)d_in[13];
    const float* b2_1  = (const float*)d_in[14];
    const float* bias1 = (const float*)d_in[15];
    const float* W_out = (const float*)d_in[16];
    const float* b_out = (const float*)d_in[17];
    float* out = (float*)d_out;

    k_split_edges<<<BNN / 2 / 256, 256>>>(edges);
    k_embed<<<(BB * NN) / 4, 256>>>(nodes, W_emb, b_emb);

    // ---- layer 0 (DIN = 64) ----
    k_wh<64><<<dim3(NN / 64, BB, EH), 128>>>(Wf0);
    k_a12<<<(CC * NN * 32) / 256, 256>>>(w1_0, b1_0, w2_0, b2_0);
    k_stats<<<dim3(4, 8, CC), 256>>>();
    k_sred<<<CC * NN / 256, 256>>>();
    k_whnT<<<dim3(NN / 64, CC), 256>>>();
    k_msg_mma<0><<<dim3(NN / 128, CC), 256>>>(bias0);

    // ---- layer 1 (DIN = 256) ----
    k_wh<256><<<dim3(NN / 64, BB, EH), 128>>>(Wf1);
    k_a12<<<(CC * NN * 32) / 256, 256>>>(w1_1, b1_1, w2_1, b2_1);
    k_stats<<<dim3(4, 8, CC), 256>>>();
    k_sred<<<CC * NN / 256, 256>>>();
    k_whnT<<<dim3(NN / 64, CC), 256>>>();
    k_msg_mma<1><<<dim3(NN / 128, CC), 256>>>(bias1);

    // ---- final reduction + output head ----
    k_reduce1<<<dim3(16, BB), 256>>>();
    k_out<<<1, 256>>>(W_out, b_out, out);
}

// round 12
// speedup vs baseline: 1.0111x; 1.0111x over previous
#include <cuda_runtime.h>
#include <cuda_fp16.h>
#include <cstdint>

typedef unsigned long long ull;

// Problem constants
#define BB 4
#define NN 2048
#define II 32
#define HH 64
#define OO 32
#define EE 2
#define HD 2
#define EH 4              // E*HD
#define CC 16             // EH*B combos
#define D1 256            // H*HD*E
#define BNN 16777216      // B*N*N
#define SLAB (NN*NN/2)    // half2 per (e,b) slab

// ---------------- scratch (device globals; no allocation) ----------------
__device__ __half2 g_edgeH2[BNN];            // exp(edge) fp16 [e][b][i][k], 67MB
__device__ float g_state0[BB * NN * HH];
__device__ float g_state1[BB * NN * D1];
__device__ float g_Wh [CC * NN * HH];
__device__ __half2 g_WhnT[CC * 64 * 1024];   // [c][d][k/2]  fp16 normalized transposed
__device__ __half2 g_E1d[CC * NN];           // (exp(a1), exp(a1)) per row i
__device__ __half2 g_F1d[CC * NN];           // (exp(.2 a1), exp(.2 a1))
__device__ __half g_E2h[CC * NN];            // exp(a2 - g) per col k
__device__ __half g_F2h[CC * NN];            // exp(.2 a2 - g)
__device__ float g_spart[8 * CC * NN];
__device__ float g_msg1[CC * NN * HH];
__device__ float g_partial[BB * 16 * HH];

// ---------------- f32x2 packed helpers (Blackwell FFMA2) ----------------
__device__ __forceinline__ ull pk2(float x) {
    ull r;
    asm("mov.b64 %0, {%1, %1};" : "=l"(r) : "f"(x));
    return r;
}
__device__ __forceinline__ void fma2(ull& d, ull a, ull b) {
    asm("fma.rn.f32x2 %0, %1, %2, %0;" : "+l"(d) : "l"(a), "l"(b));
}
__device__ __forceinline__ void upk2(ull v, float& lo, float& hi) {
    asm("mov.b64 {%0, %1}, %2;" : "=f"(lo), "=f"(hi) : "l"(v));
}

// ---------------- HMMA helper: m16n8k16 fp16 -> fp32 ----------------
__device__ __forceinline__ void mma16816(float* d,
                                         uint32_t a0, uint32_t a1,
                                         uint32_t a2, uint32_t a3,
                                         uint32_t b0, uint32_t b1) {
    asm volatile(
        "mma.sync.aligned.m16n8k16.row.col.f32.f16.f16.f32 "
        "{%0,%1,%2,%3}, {%4,%5,%6,%7}, {%8,%9}, {%0,%1,%2,%3};"
        : "+f"(d[0]), "+f"(d[1]), "+f"(d[2]), "+f"(d[3])
        : "r"(a0), "r"(a1), "r"(a2), "r"(a3), "r"(b0), "r"(b1));
}

__device__ __forceinline__ uint32_t h2u(__half2 h) {
    return *reinterpret_cast<uint32_t*>(&h);
}
// P-pair = eE * max(E1*E2, F1*F2)   (exp factorization of lrelu softmax logit)
__device__ __forceinline__ __half2 ppair(__half2 eE, __half2 E1, __half2 F1,
                                         __half2 E2, __half2 F2) {
    return __hmul2(eE, __hmax2(__hmul2(E1, E2), __hmul2(F1, F2)));
}

// ---------------- kernels ----------------

// split interleaved fp32 edges (B,N,N,E) -> two contiguous fp16 exp(edge) slabs
__global__ void k_split_edges(const float* __restrict__ edges) {
    size_t t = (size_t)blockIdx.x * blockDim.x + threadIdx.x;  // over BNN/2 float4s
    float4 v = ((const float4*)edges)[t];
    g_edgeH2[t]           = __floats2half2_rn(__expf(v.x), __expf(v.z));   // e=0
    g_edgeH2[BNN / 2 + t] = __floats2half2_rn(__expf(v.y), __expf(v.w));   // e=1
}

// state0 = nodes @ W_emb + b_emb
__global__ void k_embed(const float* __restrict__ nodes,
                        const float* __restrict__ Wemb,
                        const float* __restrict__ bemb) {
    __shared__ float sW[II * HH];
    int tid = threadIdx.x;
    for (int i = tid; i < II * HH; i += 256) sW[i] = Wemb[i];
    __syncthreads();
    int row = blockIdx.x * 4 + (tid >> 6);
    int h = tid & 63;
    const float* nr = nodes + (size_t)row * II;
    float acc = bemb[h];
#pragma unroll
    for (int d = 0; d < II; d++) acc += __ldg(&nr[d]) * sW[d * HH + h];
    g_state0[(size_t)row * HH + h] = acc;
}

// Wh[eh,b,n,:] = state @ Wf[eh]   64x64 tile, FFMA2 micro-kernel
template <int DIN>
__global__ void __launch_bounds__(128) k_wh(const float* __restrict__ Wf) {
    __shared__ float sS[64][66];
    __shared__ __align__(16) float sW[64][68];
    const float* src = (DIN == 64) ? g_state0 : g_state1;
    int tid = threadIdx.x;
    int n0 = blockIdx.x * 64;
    int b = blockIdx.y;
    int eh = blockIdx.z;
    const float* Wfe = Wf + (size_t)eh * DIN * 64;
    const float* S = src + ((size_t)b * NN + n0) * DIN;
    int ti = tid >> 3, td = tid & 7;
    int ry = tid >> 1, xs = (tid & 1) * 32;
    ull acc[16];
#pragma unroll
    for (int r = 0; r < 16; r++) acc[r] = 0ULL;

    for (int d0 = 0; d0 < DIN; d0 += 64) {
        __syncthreads();
#pragma unroll
        for (int j = 0; j < 8; j++) {
            float4 v = *(const float4*)&S[(size_t)ry * DIN + d0 + xs + 4 * j];
            sS[ry][xs + 4 * j + 0] = v.x;
            sS[ry][xs + 4 * j + 1] = v.y;
            sS[ry][xs + 4 * j + 2] = v.z;
            sS[ry][xs + 4 * j + 3] = v.w;
        }
#pragma unroll
        for (int j = 0; j < 8; j++)
            *(float4*)&sW[ry][xs + 4 * j] =
                *(const float4*)&Wfe[(size_t)(d0 + ry) * 64 + xs + 4 * j];
        __syncthreads();
#pragma unroll 8
        for (int d = 0; d < 64; d++) {
            const ull* wp = (const ull*)&sW[d][8 * td];
            ull w0 = wp[0], w1 = wp[1], w2v = wp[2], w3 = wp[3];
#pragma unroll
            for (int r = 0; r < 4; r++) {
                ull s = pk2(sS[4 * ti + r][d]);
                fma2(acc[4 * r + 0], s, w0);
                fma2(acc[4 * r + 1], s, w1);
                fma2(acc[4 * r + 2], s, w2v);
                fma2(acc[4 * r + 3], s, w3);
            }
        }
    }
    size_t base = (size_t)(eh * BB + b) * NN + n0;
#pragma unroll
    for (int r = 0; r < 4; r++) {
        float o[8];
        upk2(acc[4 * r + 0], o[0], o[1]);
        upk2(acc[4 * r + 1], o[2], o[3]);
        upk2(acc[4 * r + 2], o[4], o[5]);
        upk2(acc[4 * r + 3], o[6], o[7]);
        float* dst = &g_Wh[(base + 4 * ti + r) * 64 + 8 * td];
        *(float4*)dst = make_float4(o[0], o[1], o[2], o[3]);
        *(float4*)(dst + 4) = make_float4(o[4], o[5], o[6], o[7]);
    }
}

// a1/a2 row reductions -> factorized exp tables E1,F1 (per i) / E2,F2 (per k)
// Per-k shift g = lrelu(a2) keeps fp16 products in range; cancels in softmax.
__global__ void k_a12(const float* __restrict__ w1, const float* __restrict__ b1,
                      const float* __restrict__ w2, const float* __restrict__ b2) {
    int warp = (blockIdx.x * blockDim.x + threadIdx.x) >> 5;
    int lane = threadIdx.x & 31;
    int c = warp >> 11;
    int eh = c >> 2;
    const float* wh = g_Wh + (size_t)warp * 64;
    float x0 = wh[lane], x1 = wh[lane + 32];
    float d1 = x0 * w1[eh * 64 + lane] + x1 * w1[eh * 64 + lane + 32];
    float d2 = x0 * w2[eh * 64 + lane] + x1 * w2[eh * 64 + lane + 32];
#pragma unroll
    for (int o = 16; o; o >>= 1) {
        d1 += __shfl_down_sync(0xffffffffu, d1, o);
        d2 += __shfl_down_sync(0xffffffffu, d2, o);
    }
    if (lane == 0) {
        float a1v = d1 + b1[eh];
        float a2v = d2 + b2[eh];
        float E1 = __expf(a1v), F1 = __expf(0.2f * a1v);
        g_E1d[warp] = __floats2half2_rn(E1, E1);
        g_F1d[warp] = __floats2half2_rn(F1, F1);
        float g = fmaxf(a2v, 0.2f * a2v);
        g_E2h[warp] = __float2half_rn(__expf(a2v - g));
        g_F2h[warp] = __float2half_rn(__expf(0.2f * a2v - g));
    }
}

// partial s[k]: one block covers BOTH heads of an (e,b) slab (single edge read).
// grid (ktile=4, ichunk=8, eb=8)
__global__ void __launch_bounds__(256) k_stats() {
    __shared__ __half2 sE1a[256], sF1a[256], sE1b[256], sF1b[256];
    int eb = blockIdx.z;
    int e = eb >> 2, b = eb & 3;
    int c0 = (2 * e) * BB + b, c1 = (2 * e + 1) * BB + b;
    int tid = threadIdx.x;
    int kbase = blockIdx.x * 512;
    int i0 = blockIdx.y * 256;
    sE1a[tid] = g_E1d[c0 * NN + i0 + tid];
    sF1a[tid] = g_F1d[c0 * NN + i0 + tid];
    sE1b[tid] = g_E1d[c1 * NN + i0 + tid];
    sF1b[tid] = g_F1d[c1 * NN + i0 + tid];
    __syncthreads();
    int k = kbase + 2 * tid;
    __half2 E2a = *(const __half2*)&g_E2h[c0 * NN + k];
    __half2 F2a = *(const __half2*)&g_F2h[c0 * NN + k];
    __half2 E2b = *(const __half2*)&g_E2h[c1 * NN + k];
    __half2 F2b = *(const __half2*)&g_F2h[c1 * NN + k];
    const __half2* eg = g_edgeH2 + (size_t)eb * SLAB +
                        (size_t)i0 * (NN / 2) + (kbase >> 1) + tid;
    float s0a = 0.f, s1a = 0.f, s0b = 0.f, s1b = 0.f;
#pragma unroll 8
    for (int i = 0; i < 256; i++) {
        __half2 ev = eg[(size_t)i * (NN / 2)];
        float2 fa = __half22float2(ppair(ev, sE1a[i], sF1a[i], E2a, F2a));
        float2 fb = __half22float2(ppair(ev, sE1b[i], sF1b[i], E2b, F2b));
        s0a += fa.x; s1a += fa.y;
        s0b += fb.x; s1b += fb.y;
    }
    float2* spa = (float2*)(g_spart + ((size_t)blockIdx.y * CC + c0) * NN);
    float2* spb = (float2*)(g_spart + ((size_t)blockIdx.y * CC + c1) * NN);
    spa[(kbase >> 1) + tid] = make_float2(s0a, s1a);
    spb[(kbase >> 1) + tid] = make_float2(s0b, s1b);
}

// WhnT[c][d][k] = (Wh[c][k][d] / s[c][k]) fp16 transposed; s summed inline.
__global__ void __launch_bounds__(256) k_whnT() {
    __shared__ float tl[64][65];
    int c = blockIdx.y;
    int k0 = blockIdx.x * 64;
    int tid = threadIdx.x;
    int ky = tid >> 6, d = tid & 63;
#pragma unroll
    for (int p = 0; p < 16; p++)
        tl[4 * p + ky][d] = g_Wh[((size_t)c * NN + k0 + 4 * p + ky) * 64 + d];
    __syncthreads();
    int lam = tid & 31, dw = tid >> 5;
    float sx = 0.f, sy = 0.f;
#pragma unroll
    for (int ic = 0; ic < 8; ic++) {
        float2 p = *(const float2*)&g_spart[((size_t)ic * CC + c) * NN + k0 + 2 * lam];
        sx += p.x; sy += p.y;
    }
    float rx = __fdividef(1.f, sx), ry = __fdividef(1.f, sy);
#pragma unroll
    for (int q = 0; q < 8; q++) {
        int dd = dw * 8 + q;
        g_WhnT[(size_t)(c * 64 + dd) * 1024 + (k0 >> 1) + lam] =
            __floats2half2_rn(tl[2 * lam][dd] * rx, tl[2 * lam + 1][dd] * ry);
    }
}

// msg via HMMA m16n8k16: D[128 i, 64 d] = sum_k P[i,k] * WhnT[d,k]
// A fragments computed in registers with the factorized-exp formula (no MUFU).
template <int LAYER>
__global__ void __launch_bounds__(256) k_msg_mma(const float* __restrict__ bias) {
    int tid = threadIdx.x;
    int w = tid >> 5, lane = tid & 31;
    int grp = lane >> 2, qd = lane & 3;
    int c = blockIdx.y;
    int eh = c >> 2, b = c & 3;
    int e = eh >> 1, h = eh & 1;
    int i0 = blockIdx.x * 128;
    int iw = i0 + 16 * w;

    const __half2* eslab = g_edgeH2 + (size_t)(e * BB + b) * SLAB;
    const __half2* wT = g_WhnT + (size_t)c * 64 * 1024;
    const __half* E2p = g_E2h + c * NN;
    const __half* F2p = g_F2h + c * NN;

    __half2 E1lo = g_E1d[c * NN + iw + grp];
    __half2 F1lo = g_F1d[c * NN + iw + grp];
    __half2 E1hi = g_E1d[c * NN + iw + grp + 8];
    __half2 F1hi = g_F1d[c * NN + iw + grp + 8];

    const __half2* erow_lo = eslab + (size_t)(iw + grp) * (NN / 2);
    const __half2* erow_hi = erow_lo + (size_t)8 * (NN / 2);

    float acc[8][4];
#pragma unroll
    for (int nt = 0; nt < 8; nt++)
#pragma unroll
        for (int j = 0; j < 4; j++) acc[nt][j] = 0.f;

    // edge double-buffer
    __half2 e0 = erow_lo[qd], e1 = erow_lo[qd + 4];
    __half2 e2 = erow_hi[qd], e3 = erow_hi[qd + 4];

#pragma unroll 2
    for (int t = 0; t < 128; t++) {
        int kh = 8 * t;
        __half2 c0 = e0, c1 = e1, c2 = e2, c3 = e3;
        if (t < 127) {
            e0 = erow_lo[kh + 8 + qd]; e1 = erow_lo[kh + 8 + qd + 4];
            e2 = erow_hi[kh + 8 + qd]; e3 = erow_hi[kh + 8 + qd + 4];
        }
        __half2 E2a = *(const __half2*)&E2p[16 * t + 2 * qd];
        __half2 F2a = *(const __half2*)&F2p[16 * t + 2 * qd];
        __half2 E2b = *(const __half2*)&E2p[16 * t + 2 * qd + 8];
        __half2 F2b = *(const __half2*)&F2p[16 * t + 2 * qd + 8];

        uint32_t A0 = h2u(ppair(c0, E1lo, F1lo, E2a, F2a));  // rows 0-7,  k 0-7
        uint32_t A1 = h2u(ppair(c2, E1hi, F1hi, E2a, F2a));  // rows 8-15, k 0-7
        uint32_t A2 = h2u(ppair(c1, E1lo, F1lo, E2b, F2b));  // rows 0-7,  k 8-15
        uint32_t A3 = h2u(ppair(c3, E1hi, F1hi, E2b, F2b));  // rows 8-15, k 8-15

#pragma unroll
        for (int nt = 0; nt < 8; nt++) {
            const __half2* bp = wT + (size_t)(8 * nt + grp) * 1024 + kh + qd;
            uint32_t B0 = h2u(bp[0]);
            uint32_t B1 = h2u(bp[4]);
            mma16816(acc[nt], A0, A1, A2, A3, B0, B1);
        }
    }

    // store: acc[.][0,1] -> (row grp, cols 2qd,2qd+1); acc[.][2,3] -> row grp+8
    int gi_lo = iw + grp, gi_hi = iw + grp + 8;
#pragma unroll
    for (int nt = 0; nt < 8; nt++) {
        int col = 8 * nt + 2 * qd;
        float bx = bias[h * 64 + col], by = bias[h * 64 + col + 1];
        float2 vlo = make_float2(acc[nt][0] + bx, acc[nt][1] + by);
        float2 vhi = make_float2(acc[nt][2] + bx, acc[nt][3] + by);
        if (LAYER == 0) {
            *(float2*)&g_state1[((size_t)b * NN + gi_lo) * D1 + eh * 64 + col] = vlo;
            *(float2*)&g_state1[((size_t)b * NN + gi_hi) * D1 + eh * 64 + col] = vhi;
        } else {
            *(float2*)&g_msg1[((size_t)c * NN + gi_lo) * 64 + col] = vlo;
            *(float2*)&g_msg1[((size_t)c * NN + gi_hi) * 64 + col] = vhi;
        }
    }
}

// partial[b,chunk,h] = sum over eh and 128 n-rows of elu(msg1)
__global__ void k_reduce1() {
    int b = blockIdx.y, ch = blockIdx.x;
    int n0 = ch * 128;
    int h = threadIdx.x & 63, sub = threadIdx.x >> 6;
    float s = 0.f;
#pragma unroll
    for (int eh = 0; eh < EH; eh++) {
        const float* m = g_msg1 + ((size_t)(eh * BB + b) * NN + n0) * 64;
        for (int n = sub; n < 128; n += 4) {
            float x = m[(size_t)n * 64 + h];
            s += x > 0.f ? x : expm1f(x);
        }
    }
    __shared__ float red[256];
    red[threadIdx.x] = s;
    __syncthreads();
    if (threadIdx.x < 64)
        g_partial[(b * 16 + ch) * 64 + threadIdx.x] =
            red[threadIdx.x] + red[64 + threadIdx.x] +
            red[128 + threadIdx.x] + red[192 + threadIdx.x];
}

__global__ void k_out(const float* __restrict__ Wout,
                      const float* __restrict__ bout,
                      float* __restrict__ out) {
    __shared__ float v[BB * 64];
    int t = threadIdx.x;
    {
        int b = t >> 6, h = t & 63;
        float s = 0.f;
#pragma unroll
        for (int p = 0; p < 16; p++) s += g_partial[(b * 16 + p) * 64 + h];
        v[t] = s;
    }
    __syncthreads();
    if (t < 128) {
        int b = t >> 5, o = t & 31;
        float s = 0.f;
#pragma unroll
        for (int hh = 0; hh < 64; hh++) s += v[b * 64 + hh] * Wout[hh * OO + o];
        out[b * OO + o] = s * (1.f / 8192.f) + bout[o];
    }
}

// ---------------- launcher ----------------
extern "C" void kernel_launch(void* const* d_in, const int* in_sizes, int n_in,
                              void* d_out, int out_size) {
    const float* nodes = (const float*)d_in[0];
    const float* edges = (const float*)d_in[1];
    const float* W_emb = (const float*)d_in[2];
    const float* b_emb = (const float*)d_in[3];
    const float* Wf0   = (const float*)d_in[4];
    const float* w1_0  = (const float*)d_in[5];
    const float* b1_0  = (const float*)d_in[6];
    const float* w2_0  = (const float*)d_in[7];
    const float* b2_0  = (const float*)d_in[8];
    const float* bias0 = (const float*)d_in[9];
    const float* Wf1   = (const float*)d_in[10];
    const float* w1_1  = (const float*)d_in[11];
    const float* b1_1  = (const float*)d_in[12];
    const float* w2_1  = (const float*)d_in[13];
    const float* b2_1  = (const float*)d_in[14];
    const float* bias1 = (const float*)d_in[15];
    const float* W_out = (const float*)d_in[16];
    const float* b_out = (const float*)d_in[17];
    float* out = (float*)d_out;

    k_split_edges<<<BNN / 2 / 256, 256>>>(edges);
    k_embed<<<(BB * NN) / 4, 256>>>(nodes, W_emb, b_emb);

    // ---- layer 0 (DIN = 64) ----
    k_wh<64><<<dim3(NN / 64, BB, EH), 128>>>(Wf0);
    k_a12<<<(CC * NN * 32) / 256, 256>>>(w1_0, b1_0, w2_0, b2_0);
    k_stats<<<dim3(4, 8, 8), 256>>>();
    k_whnT<<<dim3(NN / 64, CC), 256>>>();
    k_msg_mma<0><<<dim3(NN / 128, CC), 256>>>(bias0);

    // ---- layer 1 (DIN = 256) ----
    k_wh<256><<<dim3(NN / 64, BB, EH), 128>>>(Wf1);
    k_a12<<<(CC * NN * 32) / 256, 256>>>(w1_1, b1_1, w2_1, b2_1);
    k_stats<<<dim3(4, 8, 8), 256>>>();
    k_whnT<<<dim3(NN / 64, CC), 256>>>();
    k_msg_mma<1><<<dim3(NN / 128, CC), 256>>>(bias1);

    // ---- final reduction + output head ----
    k_reduce1<<<dim3(16, BB), 256>>>();
    k_out<<<1, 256>>>(W_out, b_out, out);
}

// round 13
// speedup vs baseline: 1.4471x; 1.4313x over previous
#include <cuda_runtime.h>
#include <cuda_fp16.h>
#include <cstdint>

typedef unsigned long long ull;

// Problem constants
#define BB 4
#define NN 2048
#define II 32
#define HH 64
#define OO 32
#define EE 2
#define HD 2
#define EH 4              // E*HD
#define CC 16             // EH*B combos
#define D1 256            // H*HD*E
#define BNN 16777216      // B*N*N
#define SLAB (NN*NN/2)    // half2 per (e,b) slab

// ---------------- scratch (device globals; no allocation) ----------------
__device__ __half2 g_edgeH2[BNN];            // exp(edge) fp16 [e][b][i][k], 67MB
__device__ float g_state0[BB * NN * HH];
__device__ float g_state1[BB * NN * D1];
__device__ float g_Wh [CC * NN * HH];
__device__ __half2 g_WhnT[CC * 64 * 1024];   // [c][d][k/2]  fp16 normalized transposed
__device__ __half2 g_E1d[CC * NN];           // (exp(a1), exp(a1)) per row i
__device__ __half2 g_F1d[CC * NN];           // (exp(.2 a1), exp(.2 a1))
__device__ __half g_E2h[CC * NN];            // exp(a2 - g) per col k
__device__ __half g_F2h[CC * NN];            // exp(.2 a2 - g)
__device__ float g_spart[16 * CC * NN];
__device__ float g_msg1[CC * NN * HH];
__device__ float g_partial[BB * 16 * HH];

// ---------------- f32x2 packed helpers (Blackwell FFMA2) ----------------
__device__ __forceinline__ ull pk2(float x) {
    ull r;
    asm("mov.b64 %0, {%1, %1};" : "=l"(r) : "f"(x));
    return r;
}
__device__ __forceinline__ void fma2(ull& d, ull a, ull b) {
    asm("fma.rn.f32x2 %0, %1, %2, %0;" : "+l"(d) : "l"(a), "l"(b));
}
__device__ __forceinline__ void upk2(ull v, float& lo, float& hi) {
    asm("mov.b64 {%0, %1}, %2;" : "=f"(lo), "=f"(hi) : "l"(v));
}

// ---------------- HMMA helper: m16n8k16 fp16 -> fp32 ----------------
__device__ __forceinline__ void mma16816(float* d,
                                         uint32_t a0, uint32_t a1,
                                         uint32_t a2, uint32_t a3,
                                         uint32_t b0, uint32_t b1) {
    asm volatile(
        "mma.sync.aligned.m16n8k16.row.col.f32.f16.f16.f32 "
        "{%0,%1,%2,%3}, {%4,%5,%6,%7}, {%8,%9}, {%0,%1,%2,%3};"
        : "+f"(d[0]), "+f"(d[1]), "+f"(d[2]), "+f"(d[3])
        : "r"(a0), "r"(a1), "r"(a2), "r"(a3), "r"(b0), "r"(b1));
}

__device__ __forceinline__ uint32_t h2u(__half2 h) {
    return *reinterpret_cast<uint32_t*>(&h);
}
// P-pair = eE * max(E1*E2, F1*F2)   (exp factorization of lrelu softmax logit)
__device__ __forceinline__ __half2 ppair(__half2 eE, __half2 E1, __half2 F1,
                                         __half2 E2, __half2 F2) {
    return __hmul2(eE, __hmax2(__hmul2(E1, E2), __hmul2(F1, F2)));
}

// ---------------- async copy + ldmatrix helpers ----------------
__device__ __forceinline__ uint32_t smem_u32(const void* p) {
    uint32_t a;
    asm("{ .reg .u64 t; cvta.to.shared.u64 t, %1; cvt.u32.u64 %0, t; }"
        : "=r"(a) : "l"(p));
    return a;
}
__device__ __forceinline__ void cpa16(uint32_t dst, const void* src) {
    asm volatile("cp.async.cg.shared.global [%0], [%1], 16;" :: "r"(dst), "l"(src));
}
#define CP_COMMIT() asm volatile("cp.async.commit_group;" ::: "memory")
#define CP_WAIT1()  asm volatile("cp.async.wait_group 1;" ::: "memory")
#define CP_WAIT0()  asm volatile("cp.async.wait_group 0;" ::: "memory")
__device__ __forceinline__ void ldm_x4(uint32_t& r0, uint32_t& r1,
                                       uint32_t& r2, uint32_t& r3, uint32_t a) {
    asm volatile("ldmatrix.sync.aligned.m8n8.x4.shared.b16 {%0,%1,%2,%3}, [%4];"
        : "=r"(r0), "=r"(r1), "=r"(r2), "=r"(r3) : "r"(a));
}

// ---------------- kernels ----------------

// split interleaved fp32 edges (B,N,N,E) -> two contiguous fp16 exp(edge) slabs
__global__ void k_split_edges(const float* __restrict__ edges) {
    size_t t = (size_t)blockIdx.x * blockDim.x + threadIdx.x;  // over BNN/2 float4s
    float4 v = ((const float4*)edges)[t];
    g_edgeH2[t]           = __floats2half2_rn(__expf(v.x), __expf(v.z));   // e=0
    g_edgeH2[BNN / 2 + t] = __floats2half2_rn(__expf(v.y), __expf(v.w));   // e=1
}

// state0 = nodes @ W_emb + b_emb
__global__ void k_embed(const float* __restrict__ nodes,
                        const float* __restrict__ Wemb,
                        const float* __restrict__ bemb) {
    __shared__ float sW[II * HH];
    int tid = threadIdx.x;
    for (int i = tid; i < II * HH; i += 256) sW[i] = Wemb[i];
    __syncthreads();
    int row = blockIdx.x * 4 + (tid >> 6);
    int h = tid & 63;
    const float* nr = nodes + (size_t)row * II;
    float acc = bemb[h];
#pragma unroll
    for (int d = 0; d < II; d++) acc += __ldg(&nr[d]) * sW[d * HH + h];
    g_state0[(size_t)row * HH + h] = acc;
}

// Wh[eh,b,n,:] = state @ Wf[eh]   64x64 tile, FFMA2 micro-kernel
template <int DIN>
__global__ void __launch_bounds__(128) k_wh(const float* __restrict__ Wf) {
    __shared__ float sS[64][66];
    __shared__ __align__(16) float sW[64][68];
    const float* src = (DIN == 64) ? g_state0 : g_state1;
    int tid = threadIdx.x;
    int n0 = blockIdx.x * 64;
    int b = blockIdx.y;
    int eh = blockIdx.z;
    const float* Wfe = Wf + (size_t)eh * DIN * 64;
    const float* S = src + ((size_t)b * NN + n0) * DIN;
    int ti = tid >> 3, td = tid & 7;
    int ry = tid >> 1, xs = (tid & 1) * 32;
    ull acc[16];
#pragma unroll
    for (int r = 0; r < 16; r++) acc[r] = 0ULL;

    for (int d0 = 0; d0 < DIN; d0 += 64) {
        __syncthreads();
#pragma unroll
        for (int j = 0; j < 8; j++) {
            float4 v = *(const float4*)&S[(size_t)ry * DIN + d0 + xs + 4 * j];
            sS[ry][xs + 4 * j + 0] = v.x;
            sS[ry][xs + 4 * j + 1] = v.y;
            sS[ry][xs + 4 * j + 2] = v.z;
            sS[ry][xs + 4 * j + 3] = v.w;
        }
#pragma unroll
        for (int j = 0; j < 8; j++)
            *(float4*)&sW[ry][xs + 4 * j] =
                *(const float4*)&Wfe[(size_t)(d0 + ry) * 64 + xs + 4 * j];
        __syncthreads();
#pragma unroll 8
        for (int d = 0; d < 64; d++) {
            const ull* wp = (const ull*)&sW[d][8 * td];
            ull w0 = wp[0], w1 = wp[1], w2v = wp[2], w3 = wp[3];
#pragma unroll
            for (int r = 0; r < 4; r++) {
                ull s = pk2(sS[4 * ti + r][d]);
                fma2(acc[4 * r + 0], s, w0);
                fma2(acc[4 * r + 1], s, w1);
                fma2(acc[4 * r + 2], s, w2v);
                fma2(acc[4 * r + 3], s, w3);
            }
        }
    }
    size_t base = (size_t)(eh * BB + b) * NN + n0;
#pragma unroll
    for (int r = 0; r < 4; r++) {
        float o[8];
        upk2(acc[4 * r + 0], o[0], o[1]);
        upk2(acc[4 * r + 1], o[2], o[3]);
        upk2(acc[4 * r + 2], o[4], o[5]);
        upk2(acc[4 * r + 3], o[6], o[7]);
        float* dst = &g_Wh[(base + 4 * ti + r) * 64 + 8 * td];
        *(float4*)dst = make_float4(o[0], o[1], o[2], o[3]);
        *(float4*)(dst + 4) = make_float4(o[4], o[5], o[6], o[7]);
    }
}

// a1/a2 row reductions -> factorized exp tables E1,F1 (per i) / E2,F2 (per k)
__global__ void k_a12(const float* __restrict__ w1, const float* __restrict__ b1,
                      const float* __restrict__ w2, const float* __restrict__ b2) {
    int warp = (blockIdx.x * blockDim.x + threadIdx.x) >> 5;
    int lane = threadIdx.x & 31;
    int c = warp >> 11;
    int eh = c >> 2;
    const float* wh = g_Wh + (size_t)warp * 64;
    float x0 = wh[lane], x1 = wh[lane + 32];
    float d1 = x0 * w1[eh * 64 + lane] + x1 * w1[eh * 64 + lane + 32];
    float d2 = x0 * w2[eh * 64 + lane] + x1 * w2[eh * 64 + lane + 32];
#pragma unroll
    for (int o = 16; o; o >>= 1) {
        d1 += __shfl_down_sync(0xffffffffu, d1, o);
        d2 += __shfl_down_sync(0xffffffffu, d2, o);
    }
    if (lane == 0) {
        float a1v = d1 + b1[eh];
        float a2v = d2 + b2[eh];
        float E1 = __expf(a1v), F1 = __expf(0.2f * a1v);
        g_E1d[warp] = __floats2half2_rn(E1, E1);
        g_F1d[warp] = __floats2half2_rn(F1, F1);
        float g = fmaxf(a2v, 0.2f * a2v);
        g_E2h[warp] = __float2half_rn(__expf(a2v - g));
        g_F2h[warp] = __float2half_rn(__expf(0.2f * a2v - g));
    }
}

// partial s[k]: one block covers BOTH heads of an (e,b) slab (single edge read).
// grid (ktile=4, ichunk=16, eb=8)
__global__ void __launch_bounds__(256) k_stats() {
    __shared__ __half2 sE1a[128], sF1a[128], sE1b[128], sF1b[128];
    int eb = blockIdx.z;
    int e = eb >> 2, b = eb & 3;
    int c0 = (2 * e) * BB + b, c1 = (2 * e + 1) * BB + b;
    int tid = threadIdx.x;
    int kbase = blockIdx.x * 512;
    int i0 = blockIdx.y * 128;
    if (tid < 128) {
        sE1a[tid] = g_E1d[c0 * NN + i0 + tid];
        sF1a[tid] = g_F1d[c0 * NN + i0 + tid];
        sE1b[tid] = g_E1d[c1 * NN + i0 + tid];
        sF1b[tid] = g_F1d[c1 * NN + i0 + tid];
    }
    __syncthreads();
    int k = kbase + 2 * tid;
    __half2 E2a = *(const __half2*)&g_E2h[c0 * NN + k];
    __half2 F2a = *(const __half2*)&g_F2h[c0 * NN + k];
    __half2 E2b = *(const __half2*)&g_E2h[c1 * NN + k];
    __half2 F2b = *(const __half2*)&g_F2h[c1 * NN + k];
    const __half2* eg = g_edgeH2 + (size_t)eb * SLAB +
                        (size_t)i0 * (NN / 2) + (kbase >> 1) + tid;
    float s0a = 0.f, s1a = 0.f, s0b = 0.f, s1b = 0.f;
#pragma unroll 8
    for (int i = 0; i < 128; i++) {
        __half2 ev = eg[(size_t)i * (NN / 2)];
        float2 fa = __half22float2(ppair(ev, sE1a[i], sF1a[i], E2a, F2a));
        float2 fb = __half22float2(ppair(ev, sE1b[i], sF1b[i], E2b, F2b));
        s0a += fa.x; s1a += fa.y;
        s0b += fb.x; s1b += fb.y;
    }
    float2* spa = (float2*)(g_spart + ((size_t)blockIdx.y * CC + c0) * NN);
    float2* spb = (float2*)(g_spart + ((size_t)blockIdx.y * CC + c1) * NN);
    spa[(kbase >> 1) + tid] = make_float2(s0a, s1a);
    spb[(kbase >> 1) + tid] = make_float2(s0b, s1b);
}

// WhnT[c][d][k] = (Wh[c][k][d] / s[c][k]) fp16 transposed; s summed inline.
__global__ void __launch_bounds__(256) k_whnT() {
    __shared__ float tl[64][65];
    int c = blockIdx.y;
    int k0 = blockIdx.x * 64;
    int tid = threadIdx.x;
    int ky = tid >> 6, d = tid & 63;
#pragma unroll
    for (int p = 0; p < 16; p++)
        tl[4 * p + ky][d] = g_Wh[((size_t)c * NN + k0 + 4 * p + ky) * 64 + d];
    __syncthreads();
    int lam = tid & 31, dw = tid >> 5;
    float sx = 0.f, sy = 0.f;
#pragma unroll
    for (int ic = 0; ic < 16; ic++) {
        float2 p = *(const float2*)&g_spart[((size_t)ic * CC + c) * NN + k0 + 2 * lam];
        sx += p.x; sy += p.y;
    }
    float rx = __fdividef(1.f, sx), ry = __fdividef(1.f, sy);
#pragma unroll
    for (int q = 0; q < 8; q++) {
        int dd = dw * 8 + q;
        g_WhnT[(size_t)(c * 64 + dd) * 1024 + (k0 >> 1) + lam] =
            __floats2half2_rn(tl[2 * lam][dd] * rx, tl[2 * lam + 1][dd] * ry);
    }
}

// msg via HMMA: D[64 i, 64 d] for BOTH heads of an (e,b) slab.
// Edges read once per block; B (WhnT) staged in smem via cp.async and
// fetched as MMA fragments with ldmatrix.x4 (conflict-free, 48B row pitch).
// grid (32 i-tiles, 8 eb), 128 threads = 4 warps x 16 rows.
#define BTILE 3072   // 64 rows * 48B pitch
template <int LAYER>
__global__ void __launch_bounds__(128) k_msg_mma(const float* __restrict__ bias) {
    __shared__ __align__(16) char sB[2][2][BTILE];   // [buf][head][row*48]
    int tid = threadIdx.x;
    int w = tid >> 5, lane = tid & 31;
    int grp = lane >> 2, qd = lane & 3;
    int eb = blockIdx.y;
    int e = eb >> 2, b = eb & 3;
    int c0 = (2 * e) * BB + b, c1 = (2 * e + 1) * BB + b;
    int i0 = blockIdx.x * 64;
    int iw = i0 + 16 * w;

    uint32_t sBb = smem_u32(sB);

    const __half2* eslab = g_edgeH2 + (size_t)eb * SLAB;
    const __half2* wT0 = g_WhnT + (size_t)c0 * 64 * 1024;
    const __half2* wT1 = g_WhnT + (size_t)c1 * 64 * 1024;
    const __half* E2p0 = g_E2h + c0 * NN;
    const __half* F2p0 = g_F2h + c0 * NN;
    const __half* E2p1 = g_E2h + c1 * NN;
    const __half* F2p1 = g_F2h + c1 * NN;

    __half2 E1lo0 = g_E1d[c0 * NN + iw + grp];
    __half2 F1lo0 = g_F1d[c0 * NN + iw + grp];
    __half2 E1hi0 = g_E1d[c0 * NN + iw + grp + 8];
    __half2 F1hi0 = g_F1d[c0 * NN + iw + grp + 8];
    __half2 E1lo1 = g_E1d[c1 * NN + iw + grp];
    __half2 F1lo1 = g_F1d[c1 * NN + iw + grp];
    __half2 E1hi1 = g_E1d[c1 * NN + iw + grp + 8];
    __half2 F1hi1 = g_F1d[c1 * NN + iw + grp + 8];

    const __half2* erow_lo = eslab + (size_t)(iw + grp) * (NN / 2);
    const __half2* erow_hi = erow_lo + (size_t)8 * (NN / 2);

    // staging mapping: thread -> (row d, 16B half)
    int sd = tid >> 1, spart = tid & 1;
    uint32_t sdst = sBb + sd * 48 + spart * 16;
    const __half2* ssrc0 = wT0 + (size_t)sd * 1024 + 4 * spart;
    const __half2* ssrc1 = wT1 + (size_t)sd * 1024 + 4 * spart;

    // ldmatrix lane address pieces: call j covers nt {2j, 2j+1}, frags {B0,B1}
    int m = lane >> 3;                 // matrix index 0..3
    int rr = lane & 7;
    uint32_t lmLane = (uint32_t)((8 * (m >> 1) + rr) * 48 + (m & 1) * 16);

    float acc[2][8][4];
#pragma unroll
    for (int h = 0; h < 2; h++)
#pragma unroll
        for (int nt = 0; nt < 8; nt++)
#pragma unroll
            for (int j = 0; j < 4; j++) acc[h][nt][j] = 0.f;

    // prologue: stage tile 0
    cpa16(sdst, ssrc0);
    cpa16(sdst + BTILE, ssrc1);
    CP_COMMIT();

    // edge register prefetch
    __half2 e0 = erow_lo[qd], e1 = erow_lo[qd + 4];
    __half2 e2 = erow_hi[qd], e3 = erow_hi[qd + 4];

    for (int t = 0; t < 128; t++) {
        int buf = t & 1;
        int kh = 8 * t;
        __half2 ce0 = e0, ce1 = e1, ce2 = e2, ce3 = e3;
        if (t < 127) {
            e0 = erow_lo[kh + 8 + qd]; e1 = erow_lo[kh + 8 + qd + 4];
            e2 = erow_hi[kh + 8 + qd]; e3 = erow_hi[kh + 8 + qd + 4];
            // stage tile t+1 into alternate buffer
            uint32_t d2 = sdst + (buf ^ 1) * (2 * BTILE);
            cpa16(d2, ssrc0 + kh + 8);
            cpa16(d2 + BTILE, ssrc1 + kh + 8);
            CP_COMMIT();
            CP_WAIT1();
        } else {
            CP_WAIT0();
        }
        __syncthreads();   // tile t staged & visible

        // A fragments (both heads) from shared edge registers
        __half2 E2a0 = *(const __half2*)&E2p0[16 * t + 2 * qd];
        __half2 F2a0 = *(const __half2*)&F2p0[16 * t + 2 * qd];
        __half2 E2b0 = *(const __half2*)&E2p0[16 * t + 2 * qd + 8];
        __half2 F2b0 = *(const __half2*)&F2p0[16 * t + 2 * qd + 8];
        __half2 E2a1 = *(const __half2*)&E2p1[16 * t + 2 * qd];
        __half2 F2a1 = *(const __half2*)&F2p1[16 * t + 2 * qd];
        __half2 E2b1 = *(const __half2*)&E2p1[16 * t + 2 * qd + 8];
        __half2 F2b1 = *(const __half2*)&F2p1[16 * t + 2 * qd + 8];

        uint32_t A0h0 = h2u(ppair(ce0, E1lo0, F1lo0, E2a0, F2a0));
        uint32_t A1h0 = h2u(ppair(ce2, E1hi0, F1hi0, E2a0, F2a0));
        uint32_t A2h0 = h2u(ppair(ce1, E1lo0, F1lo0, E2b0, F2b0));
        uint32_t A3h0 = h2u(ppair(ce3, E1hi0, F1hi0, E2b0, F2b0));
        uint32_t A0h1 = h2u(ppair(ce0, E1lo1, F1lo1, E2a1, F2a1));
        uint32_t A1h1 = h2u(ppair(ce2, E1hi1, F1hi1, E2a1, F2a1));
        uint32_t A2h1 = h2u(ppair(ce1, E1lo1, F1lo1, E2b1, F2b1));
        uint32_t A3h1 = h2u(ppair(ce3, E1hi1, F1hi1, E2b1, F2b1));

        // B fragments via ldmatrix from staged tiles
        uint32_t Bf[2][8][2];
        uint32_t tb0 = sBb + buf * (2 * BTILE) + lmLane;
        uint32_t tb1 = tb0 + BTILE;
#pragma unroll
        for (int j = 0; j < 4; j++) {
            ldm_x4(Bf[0][2 * j][0], Bf[0][2 * j][1],
                   Bf[0][2 * j + 1][0], Bf[0][2 * j + 1][1], tb0 + j * 768);
            ldm_x4(Bf[1][2 * j][0], Bf[1][2 * j][1],
                   Bf[1][2 * j + 1][0], Bf[1][2 * j + 1][1], tb1 + j * 768);
        }
        __syncthreads();   // all warps done reading buf

#pragma unroll
        for (int nt = 0; nt < 8; nt++) {
            mma16816(acc[0][nt], A0h0, A1h0, A2h0, A3h0, Bf[0][nt][0], Bf[0][nt][1]);
            mma16816(acc[1][nt], A0h1, A1h1, A2h1, A3h1, Bf[1][nt][0], Bf[1][nt][1]);
        }
    }

    // store both heads
    int gi_lo = iw + grp, gi_hi = iw + grp + 8;
#pragma unroll
    for (int h = 0; h < 2; h++) {
        int c = h ? c1 : c0;
        int eh = 2 * e + h;
#pragma unroll
        for (int nt = 0; nt < 8; nt++) {
            int col = 8 * nt + 2 * qd;
            float bx = bias[h * 64 + col], by = bias[h * 64 + col + 1];
            float2 vlo = make_float2(acc[h][nt][0] + bx, acc[h][nt][1] + by);
            float2 vhi = make_float2(acc[h][nt][2] + bx, acc[h][nt][3] + by);
            if (LAYER == 0) {
                *(float2*)&g_state1[((size_t)b * NN + gi_lo) * D1 + eh * 64 + col] = vlo;
                *(float2*)&g_state1[((size_t)b * NN + gi_hi) * D1 + eh * 64 + col] = vhi;
            } else {
                *(float2*)&g_msg1[((size_t)c * NN + gi_lo) * 64 + col] = vlo;
                *(float2*)&g_msg1[((size_t)c * NN + gi_hi) * 64 + col] = vhi;
            }
        }
    }
}

// partial[b,chunk,h] = sum over eh and 128 n-rows of elu(msg1)
__global__ void k_reduce1() {
    int b = blockIdx.y, ch = blockIdx.x;
    int n0 = ch * 128;
    int h = threadIdx.x & 63, sub = threadIdx.x >> 6;
    float s = 0.f;
#pragma unroll
    for (int eh = 0; eh < EH; eh++) {
        const float* m = g_msg1 + ((size_t)(eh * BB + b) * NN + n0) * 64;
        for (int n = sub; n < 128; n += 4) {
            float x = m[(size_t)n * 64 + h];
            s += x > 0.f ? x : expm1f(x);
        }
    }
    __shared__ float red[256];
    red[threadIdx.x] = s;
    __syncthreads();
    if (threadIdx.x < 64)
        g_partial[(b * 16 + ch) * 64 + threadIdx.x] =
            red[threadIdx.x] + red[64 + threadIdx.x] +
            red[128 + threadIdx.x] + red[192 + threadIdx.x];
}

__global__ void k_out(const float* __restrict__ Wout,
                      const float* __restrict__ bout,
                      float* __restrict__ out) {
    __shared__ float v[BB * 64];
    int t = threadIdx.x;
    {
        int b = t >> 6, h = t & 63;
        float s = 0.f;
#pragma unroll
        for (int p = 0; p < 16; p++) s += g_partial[(b * 16 + p) * 64 + h];
        v[t] = s;
    }
    __syncthreads();
    if (t < 128) {
        int b = t >> 5, o = t & 31;
        float s = 0.f;
#pragma unroll
        for (int hh = 0; hh < 64; hh++) s += v[b * 64 + hh] * Wout[hh * OO + o];
        out[b * OO + o] = s * (1.f / 8192.f) + bout[o];
    }
}

// ---------------- launcher ----------------
extern "C" void kernel_launch(void* const* d_in, const int* in_sizes, int n_in,
                              void* d_out, int out_size) {
    const float* nodes = (const float*)d_in[0];
    const float* edges = (const float*)d_in[1];
    const float* W_emb = (const float*)d_in[2];
    const float* b_emb = (const float*)d_in[3];
    const float* Wf0   = (const float*)d_in[4];
    const float* w1_0  = (const float*)d_in[5];
    const float* b1_0  = (const float*)d_in[6];
    const float* w2_0  = (const float*)d_in[7];
    const float* b2_0  = (const float*)d_in[8];
    const float* bias0 = (const float*)d_in[9];
    const float* Wf1   = (const float*)d_in[10];
    const float* w1_1  = (const float*)d_in[11];
    const float* b1_1  = (const float*)d_in[12];
    const float* w2_1  = (const float*)d_in[13];
    const float* b2_1  = (const float*)d_in[14];
    const float* bias1 = (const float*)d_in[15];
    const float* W_out = (const float*)d_in[16];
    const float* b_out = (const float*)d_in[17];
    float* out = (float*)d_out;

    k_split_edges<<<BNN / 2 / 256, 256>>>(edges);
    k_embed<<<(BB * NN) / 4, 256>>>(nodes, W_emb, b_emb);

    // ---- layer 0 (DIN = 64) ----
    k_wh<64><<<dim3(NN / 64, BB, EH), 128>>>(Wf0);
    k_a12<<<(CC * NN * 32) / 256, 256>>>(w1_0, b1_0, w2_0, b2_0);
    k_stats<<<dim3(4, 16, 8), 256>>>();
    k_whnT<<<dim3(NN / 64, CC), 256>>>();
    k_msg_mma<0><<<dim3(NN / 64, 8), 128>>>(bias0);

    // ---- layer 1 (DIN = 256) ----
    k_wh<256><<<dim3(NN / 64, BB, EH), 128>>>(Wf1);
    k_a12<<<(CC * NN * 32) / 256, 256>>>(w1_1, b1_1, w2_1, b2_1);
    k_stats<<<dim3(4, 16, 8), 256>>>();
    k_whnT<<<dim3(NN / 64, CC), 256>>>();
    k_msg_mma<1><<<dim3(NN / 64, 8), 128>>>(bias1);

    // ---- final reduction + output head ----
    k_reduce1<<<dim3(16, BB), 256>>>();
    k_out<<<1, 256>>>(W_out, b_out, out);
}

// round 14
// speedup vs baseline: 1.5779x; 1.0904x over previous
#include <cuda_runtime.h>
#include <cuda_fp16.h>
#include <cstdint>

typedef unsigned long long ull;

// Problem constants
#define BB 4
#define NN 2048
#define II 32
#define HH 64
#define OO 32
#define EE 2
#define HD 2
#define EH 4              // E*HD
#define CC 16             // EH*B combos
#define D1 256            // H*HD*E
#define BNN 16777216      // B*N*N
#define SLAB (NN*NN/2)    // half2 per (e,b) slab

// ---------------- scratch (device globals; no allocation) ----------------
__device__ __align__(16) __half2 g_edgeH2[BNN];   // exp(edge) fp16 [e][b][i][k]
__device__ float g_state0[BB * NN * HH];
__device__ float g_state1[BB * NN * D1];
__device__ float g_Wh [CC * NN * HH];
__device__ __align__(16) __half2 g_WhnT[CC * 64 * 1024];  // [c][d][k/2]
__device__ __align__(16) __half2 g_E1d[CC * NN];  // (exp(a1), exp(a1)) per row i
__device__ __align__(16) __half2 g_F1d[CC * NN];  // (exp(.2 a1), ...)
__device__ __align__(16) __half g_E2h[CC * NN];   // exp(a2 - g) per col k
__device__ __align__(16) __half g_F2h[CC * NN];   // exp(.2 a2 - g)
__device__ float g_spart[32 * CC * NN];
__device__ float g_msg1[CC * NN * HH];
__device__ float g_partial[BB * 16 * HH];

// ---------------- f32x2 packed helpers (Blackwell FFMA2) ----------------
__device__ __forceinline__ ull pk2(float x) {
    ull r;
    asm("mov.b64 %0, {%1, %1};" : "=l"(r) : "f"(x));
    return r;
}
__device__ __forceinline__ void fma2(ull& d, ull a, ull b) {
    asm("fma.rn.f32x2 %0, %1, %2, %0;" : "+l"(d) : "l"(a), "l"(b));
}
__device__ __forceinline__ void upk2(ull v, float& lo, float& hi) {
    asm("mov.b64 {%0, %1}, %2;" : "=f"(lo), "=f"(hi) : "l"(v));
}

// ---------------- HMMA helper: m16n8k16 fp16 -> fp32 ----------------
__device__ __forceinline__ void mma16816(float* d,
                                         uint32_t a0, uint32_t a1,
                                         uint32_t a2, uint32_t a3,
                                         uint32_t b0, uint32_t b1) {
    asm volatile(
        "mma.sync.aligned.m16n8k16.row.col.f32.f16.f16.f32 "
        "{%0,%1,%2,%3}, {%4,%5,%6,%7}, {%8,%9}, {%0,%1,%2,%3};"
        : "+f"(d[0]), "+f"(d[1]), "+f"(d[2]), "+f"(d[3])
        : "r"(a0), "r"(a1), "r"(a2), "r"(a3), "r"(b0), "r"(b1));
}

__device__ __forceinline__ uint32_t h2u(__half2 h) {
    return *reinterpret_cast<uint32_t*>(&h);
}
// P-pair = eE * max(E1*E2, F1*F2)   (exp factorization of lrelu softmax logit)
__device__ __forceinline__ __half2 ppair(__half2 eE, __half2 E1, __half2 F1,
                                         __half2 E2, __half2 F2) {
    return __hmul2(eE, __hmax2(__hmul2(E1, E2), __hmul2(F1, F2)));
}

// ---------------- async copy + ldmatrix helpers ----------------
__device__ __forceinline__ uint32_t smem_u32(const void* p) {
    uint32_t a;
    asm("{ .reg .u64 t; cvta.to.shared.u64 t, %1; cvt.u32.u64 %0, t; }"
        : "=r"(a) : "l"(p));
    return a;
}
__device__ __forceinline__ void cpa16(uint32_t dst, const void* src) {
    asm volatile("cp.async.cg.shared.global [%0], [%1], 16;" :: "r"(dst), "l"(src));
}
#define CP_COMMIT() asm volatile("cp.async.commit_group;" ::: "memory")
#define CP_WAIT1()  asm volatile("cp.async.wait_group 1;" ::: "memory")
#define CP_WAIT0()  asm volatile("cp.async.wait_group 0;" ::: "memory")
__device__ __forceinline__ void ldm_x4(uint32_t& r0, uint32_t& r1,
                                       uint32_t& r2, uint32_t& r3, uint32_t a) {
    asm volatile("ldmatrix.sync.aligned.m8n8.x4.shared.b16 {%0,%1,%2,%3}, [%4];"
        : "=r"(r0), "=r"(r1), "=r"(r2), "=r"(r3) : "r"(a));
}

// ---------------- kernels ----------------

// split interleaved fp32 edges (B,N,N,E) -> two contiguous fp16 exp(edge) slabs
__global__ void k_split_edges(const float* __restrict__ edges) {
    size_t t = (size_t)blockIdx.x * blockDim.x + threadIdx.x;  // over BNN/2 float4s
    float4 v = ((const float4*)edges)[t];
    g_edgeH2[t]           = __floats2half2_rn(__expf(v.x), __expf(v.z));   // e=0
    g_edgeH2[BNN / 2 + t] = __floats2half2_rn(__expf(v.y), __expf(v.w));   // e=1
}

// state0 = nodes @ W_emb + b_emb
__global__ void k_embed(const float* __restrict__ nodes,
                        const float* __restrict__ Wemb,
                        const float* __restrict__ bemb) {
    __shared__ float sW[II * HH];
    int tid = threadIdx.x;
    for (int i = tid; i < II * HH; i += 256) sW[i] = Wemb[i];
    __syncthreads();
    int row = blockIdx.x * 4 + (tid >> 6);
    int h = tid & 63;
    const float* nr = nodes + (size_t)row * II;
    float acc = bemb[h];
#pragma unroll
    for (int d = 0; d < II; d++) acc += __ldg(&nr[d]) * sW[d * HH + h];
    g_state0[(size_t)row * HH + h] = acc;
}

// Wh[eh,b,n,:] = state @ Wf[eh]  (FFMA2 micro-kernel) + FUSED a1/a2 exp tables
template <int DIN>
__global__ void __launch_bounds__(128) k_wh(const float* __restrict__ Wf,
                                            const float* __restrict__ w1,
                                            const float* __restrict__ b1,
                                            const float* __restrict__ w2,
                                            const float* __restrict__ b2) {
    __shared__ float sS[64][66];
    __shared__ __align__(16) float sW[64][68];
    __shared__ float w1s[64], w2s[64];
    const float* src = (DIN == 64) ? g_state0 : g_state1;
    int tid = threadIdx.x;
    int n0 = blockIdx.x * 64;
    int b = blockIdx.y;
    int eh = blockIdx.z;
    const float* Wfe = Wf + (size_t)eh * DIN * 64;
    const float* S = src + ((size_t)b * NN + n0) * DIN;
    int ti = tid >> 3, td = tid & 7;
    int ry = tid >> 1, xs = (tid & 1) * 32;
    if (tid < 64) w1s[tid] = w1[eh * 64 + tid];
    else if (tid < 128) w2s[tid - 64] = w2[eh * 64 + tid - 64];
    ull acc[16];
#pragma unroll
    for (int r = 0; r < 16; r++) acc[r] = 0ULL;

    for (int d0 = 0; d0 < DIN; d0 += 64) {
        __syncthreads();
#pragma unroll
        for (int j = 0; j < 8; j++) {
            float4 v = *(const float4*)&S[(size_t)ry * DIN + d0 + xs + 4 * j];
            sS[ry][xs + 4 * j + 0] = v.x;
            sS[ry][xs + 4 * j + 1] = v.y;
            sS[ry][xs + 4 * j + 2] = v.z;
            sS[ry][xs + 4 * j + 3] = v.w;
        }
#pragma unroll
        for (int j = 0; j < 8; j++)
            *(float4*)&sW[ry][xs + 4 * j] =
                *(const float4*)&Wfe[(size_t)(d0 + ry) * 64 + xs + 4 * j];
        __syncthreads();
#pragma unroll 8
        for (int d = 0; d < 64; d++) {
            const ull* wp = (const ull*)&sW[d][8 * td];
            ull w0 = wp[0], w1v = wp[1], w2v = wp[2], w3 = wp[3];
#pragma unroll
            for (int r = 0; r < 4; r++) {
                ull s = pk2(sS[4 * ti + r][d]);
                fma2(acc[4 * r + 0], s, w0);
                fma2(acc[4 * r + 1], s, w1v);
                fma2(acc[4 * r + 2], s, w2v);
                fma2(acc[4 * r + 3], s, w3);
            }
        }
    }
    int c = eh * BB + b;
    size_t base = (size_t)c * NN + n0;
    float b1v = b1[eh], b2v = b2[eh];
#pragma unroll
    for (int r = 0; r < 4; r++) {
        float o[8];
        upk2(acc[4 * r + 0], o[0], o[1]);
        upk2(acc[4 * r + 1], o[2], o[3]);
        upk2(acc[4 * r + 2], o[4], o[5]);
        upk2(acc[4 * r + 3], o[6], o[7]);
        float* dst = &g_Wh[(base + 4 * ti + r) * 64 + 8 * td];
        *(float4*)dst = make_float4(o[0], o[1], o[2], o[3]);
        *(float4*)(dst + 4) = make_float4(o[4], o[5], o[6], o[7]);
        // fused a1/a2 dot products
        float p1 = 0.f, p2 = 0.f;
#pragma unroll
        for (int j = 0; j < 8; j++) {
            p1 += o[j] * w1s[8 * td + j];
            p2 += o[j] * w2s[8 * td + j];
        }
#pragma unroll
        for (int off = 4; off; off >>= 1) {
            p1 += __shfl_xor_sync(0xffffffffu, p1, off);
            p2 += __shfl_xor_sync(0xffffffffu, p2, off);
        }
        if (td == 0) {
            size_t n = base + 4 * ti + r;
            float a1v = p1 + b1v;
            float a2v = p2 + b2v;
            float E1 = __expf(a1v), F1 = __expf(0.2f * a1v);
            g_E1d[n] = __floats2half2_rn(E1, E1);
            g_F1d[n] = __floats2half2_rn(F1, F1);
            float g = fmaxf(a2v, 0.2f * a2v);
            g_E2h[n] = __float2half_rn(__expf(a2v - g));
            g_F2h[n] = __float2half_rn(__expf(0.2f * a2v - g));
        }
    }
}

// partial s[k]: both heads of an (e,b) slab, 4 k per thread (8B edge loads).
// grid (ktile=2, ichunk=32, eb=8)
__global__ void __launch_bounds__(256) k_stats() {
    __shared__ __half2 sE1a[64], sF1a[64], sE1b[64], sF1b[64];
    int eb = blockIdx.z;
    int e = eb >> 2, b = eb & 3;
    int c0 = (2 * e) * BB + b, c1 = (2 * e + 1) * BB + b;
    int tid = threadIdx.x;
    int kbase = blockIdx.x * 1024;
    int i0 = blockIdx.y * 64;
    if (tid < 64) {
        sE1a[tid] = g_E1d[c0 * NN + i0 + tid];
        sF1a[tid] = g_F1d[c0 * NN + i0 + tid];
        sE1b[tid] = g_E1d[c1 * NN + i0 + tid];
        sF1b[tid] = g_F1d[c1 * NN + i0 + tid];
    }
    __syncthreads();
    int k = kbase + 4 * tid;
    __half2 E2a0, E2a1, F2a0, F2a1, E2b0, E2b1, F2b0, F2b1;
    { ull v = *(const ull*)&g_E2h[c0 * NN + k];
      E2a0 = ((__half2*)&v)[0]; E2a1 = ((__half2*)&v)[1]; }
    { ull v = *(const ull*)&g_F2h[c0 * NN + k];
      F2a0 = ((__half2*)&v)[0]; F2a1 = ((__half2*)&v)[1]; }
    { ull v = *(const ull*)&g_E2h[c1 * NN + k];
      E2b0 = ((__half2*)&v)[0]; E2b1 = ((__half2*)&v)[1]; }
    { ull v = *(const ull*)&g_F2h[c1 * NN + k];
      F2b0 = ((__half2*)&v)[0]; F2b1 = ((__half2*)&v)[1]; }
    const ull* egg = (const ull*)(g_edgeH2 + (size_t)eb * SLAB) +
                     (size_t)i0 * (NN / 4) + (k >> 2);
    float s0a = 0.f, s1a = 0.f, s2a = 0.f, s3a = 0.f;
    float s0b = 0.f, s1b = 0.f, s2b = 0.f, s3b = 0.f;
#pragma unroll 8
    for (int i = 0; i < 64; i++) {
        ull ev = egg[(size_t)i * (NN / 4)];
        __half2 e0 = ((__half2*)&ev)[0], e1 = ((__half2*)&ev)[1];
        __half2 ea = sE1a[i], fa = sF1a[i], ebv = sE1b[i], fb = sF1b[i];
        float2 a0 = __half22float2(ppair(e0, ea, fa, E2a0, F2a0));
        float2 a1 = __half22float2(ppair(e1, ea, fa, E2a1, F2a1));
        float2 b0 = __half22float2(ppair(e0, ebv, fb, E2b0, F2b0));
        float2 b1 = __half22float2(ppair(e1, ebv, fb, E2b1, F2b1));
        s0a += a0.x; s1a += a0.y; s2a += a1.x; s3a += a1.y;
        s0b += b0.x; s1b += b0.y; s2b += b1.x; s3b += b1.y;
    }
    *(float4*)&g_spart[((size_t)blockIdx.y * CC + c0) * NN + k] =
        make_float4(s0a, s1a, s2a, s3a);
    *(float4*)&g_spart[((size_t)blockIdx.y * CC + c1) * NN + k] =
        make_float4(s0b, s1b, s2b, s3b);
}

// WhnT[c][d][k] = (Wh[c][k][d] / s[c][k]) fp16 transposed; s summed inline.
__global__ void __launch_bounds__(256) k_whnT() {
    __shared__ float tl[64][65];
    int c = blockIdx.y;
    int k0 = blockIdx.x * 64;
    int tid = threadIdx.x;
    int ky = tid >> 6, d = tid & 63;
#pragma unroll
    for (int p = 0; p < 16; p++)
        tl[4 * p + ky][d] = g_Wh[((size_t)c * NN + k0 + 4 * p + ky) * 64 + d];
    __syncthreads();
    int lam = tid & 31, dw = tid >> 5;
    float sx = 0.f, sy = 0.f;
#pragma unroll
    for (int ic = 0; ic < 32; ic++) {
        float2 p = *(const float2*)&g_spart[((size_t)ic * CC + c) * NN + k0 + 2 * lam];
        sx += p.x; sy += p.y;
    }
    float rx = __fdividef(1.f, sx), ry = __fdividef(1.f, sy);
#pragma unroll
    for (int q = 0; q < 8; q++) {
        int dd = dw * 8 + q;
        g_WhnT[(size_t)(c * 64 + dd) * 1024 + (k0 >> 1) + lam] =
            __floats2half2_rn(tl[2 * lam][dd] * rx, tl[2 * lam + 1][dd] * ry);
    }
}

// msg via HMMA: D[128 i, 64 d] for BOTH heads of an (e,b) slab.
// 8 warps: warp = (ig, head); each warp covers 32 i-rows x 64 d of its head,
// reusing each B fragment across two A fragments (halves smem bytes/MMA).
// 3-stage cp.async ring -> ONE __syncthreads per k-tile.
// grid (16 i-tiles, 8 eb), 256 threads.
#define BTILE 3072   // 64 rows * 48B pitch
template <int LAYER>
__global__ void __launch_bounds__(256) k_msg_mma(const float* __restrict__ bias) {
    __shared__ __align__(16) char sB[3][2][BTILE];   // [buf][head][row*48]
    int tid = threadIdx.x;
    int w = tid >> 5, lane = tid & 31;
    int grp = lane >> 2, qd = lane & 3;
    int head = w & 1, ig = w >> 1;
    int eb = blockIdx.y;
    int e = eb >> 2, b = eb & 3;
    int c = (2 * e + head) * BB + b;
    int i0 = blockIdx.x * 128;
    int iw = i0 + 32 * ig;

    uint32_t sBb = smem_u32(sB);

    const __half2* eslab = g_edgeH2 + (size_t)eb * SLAB;
    const __half* E2p = g_E2h + c * NN;
    const __half* F2p = g_F2h + c * NN;

    __half2 E1r0 = g_E1d[c * NN + iw + grp];
    __half2 F1r0 = g_F1d[c * NN + iw + grp];
    __half2 E1r1 = g_E1d[c * NN + iw + grp + 8];
    __half2 F1r1 = g_F1d[c * NN + iw + grp + 8];
    __half2 E1r2 = g_E1d[c * NN + iw + grp + 16];
    __half2 F1r2 = g_F1d[c * NN + iw + grp + 16];
    __half2 E1r3 = g_E1d[c * NN + iw + grp + 24];
    __half2 F1r3 = g_F1d[c * NN + iw + grp + 24];

    const __half2* er0 = eslab + (size_t)(iw + grp) * (NN / 2);
    const __half2* er1 = er0 + (size_t)8 * (NN / 2);
    const __half2* er2 = er0 + (size_t)16 * (NN / 2);
    const __half2* er3 = er0 + (size_t)24 * (NN / 2);

    // staging: 256 threads -> one 16B cp.async each per tile (64 rows x 2 halves x 2 heads)
    int sd = tid >> 2, shh = (tid >> 1) & 1, sp = tid & 1;
    uint32_t sdst = sBb + shh * BTILE + sd * 48 + sp * 16;
    const __half2* ssrc = g_WhnT + (size_t)((2 * e + shh) * BB + b) * 64 * 1024 +
                          (size_t)sd * 1024 + 4 * sp;

    // ldmatrix lane address
    int m = lane >> 3, rr = lane & 7;
    uint32_t lmLane = (uint32_t)((8 * (m >> 1) + rr) * 48 + (m & 1) * 16) + head * BTILE;

    float accA[8][4], accB[8][4];
#pragma unroll
    for (int nt = 0; nt < 8; nt++)
#pragma unroll
        for (int j = 0; j < 4; j++) { accA[nt][j] = 0.f; accB[nt][j] = 0.f; }

    // prologue: stage tile 0 into buf 0
    cpa16(sdst, ssrc);
    CP_COMMIT();

    // edge register prefetch (t = 0)
    __half2 p0a = er0[qd], p0b = er0[qd + 4];
    __half2 p1a = er1[qd], p1b = er1[qd + 4];
    __half2 p2a = er2[qd], p2b = er2[qd + 4];
    __half2 p3a = er3[qd], p3b = er3[qd + 4];

    for (int t = 0; t < 128; t++) {
        int buf = t - (t / 3) * 3;      // t % 3
        int kh = 8 * t;
        __half2 c0a = p0a, c0b = p0b, c1a = p1a, c1b = p1b;
        __half2 c2a = p2a, c2b = p2b, c3a = p3a, c3b = p3b;
        if (t < 127) {
            p0a = er0[kh + 8 + qd]; p0b = er0[kh + 8 + qd + 4];
            p1a = er1[kh + 8 + qd]; p1b = er1[kh + 8 + qd + 4];
            p2a = er2[kh + 8 + qd]; p2b = er2[kh + 8 + qd + 4];
            p3a = er3[kh + 8 + qd]; p3b = er3[kh + 8 + qd + 4];
            int nbuf = (t + 1) - ((t + 1) / 3) * 3;
            cpa16(sdst + nbuf * (2 * BTILE), ssrc + kh + 8);
            CP_COMMIT();
            CP_WAIT1();
        } else {
            CP_WAIT0();
        }
        __syncthreads();   // tile t staged & prior ldmatrix of this buf drained

        __half2 E2a = *(const __half2*)&E2p[16 * t + 2 * qd];
        __half2 F2a = *(const __half2*)&F2p[16 * t + 2 * qd];
        __half2 E2b = *(const __half2*)&E2p[16 * t + 2 * qd + 8];
        __half2 F2b = *(const __half2*)&F2p[16 * t + 2 * qd + 8];

        uint32_t A0 = h2u(ppair(c0a, E1r0, F1r0, E2a, F2a));
        uint32_t A1 = h2u(ppair(c1a, E1r1, F1r1, E2a, F2a));
        uint32_t A2 = h2u(ppair(c0b, E1r0, F1r0, E2b, F2b));
        uint32_t A3 = h2u(ppair(c1b, E1r1, F1r1, E2b, F2b));
        uint32_t A4 = h2u(ppair(c2a, E1r2, F1r2, E2a, F2a));
        uint32_t A5 = h2u(ppair(c3a, E1r3, F1r3, E2a, F2a));
        uint32_t A6 = h2u(ppair(c2b, E1r2, F1r2, E2b, F2b));
        uint32_t A7 = h2u(ppair(c3b, E1r3, F1r3, E2b, F2b));

        // B fragments for this warp's head only
        uint32_t Bf[8][2];
        uint32_t tb = sBb + buf * (2 * BTILE) + lmLane;
#pragma unroll
        for (int j = 0; j < 4; j++)
            ldm_x4(Bf[2 * j][0], Bf[2 * j][1],
                   Bf[2 * j + 1][0], Bf[2 * j + 1][1], tb + j * 768);

#pragma unroll
        for (int nt = 0; nt < 8; nt++) {
            mma16816(accA[nt], A0, A1, A2, A3, Bf[nt][0], Bf[nt][1]);
            mma16816(accB[nt], A4, A5, A6, A7, Bf[nt][0], Bf[nt][1]);
        }
    }

    int gi0 = iw + grp, gi1 = iw + grp + 8;
    int gi2 = iw + grp + 16, gi3 = iw + grp + 24;
    int eh = 2 * e + head;
#pragma unroll
    for (int nt = 0; nt < 8; nt++) {
        int col = 8 * nt + 2 * qd;
        float bx = bias[head * 64 + col], by = bias[head * 64 + col + 1];
        float2 v0 = make_float2(accA[nt][0] + bx, accA[nt][1] + by);
        float2 v1 = make_float2(accA[nt][2] + bx, accA[nt][3] + by);
        float2 v2 = make_float2(accB[nt][0] + bx, accB[nt][1] + by);
        float2 v3 = make_float2(accB[nt][2] + bx, accB[nt][3] + by);
        if (LAYER == 0) {
            *(float2*)&g_state1[((size_t)b * NN + gi0) * D1 + eh * 64 + col] = v0;
            *(float2*)&g_state1[((size_t)b * NN + gi1) * D1 + eh * 64 + col] = v1;
            *(float2*)&g_state1[((size_t)b * NN + gi2) * D1 + eh * 64 + col] = v2;
            *(float2*)&g_state1[((size_t)b * NN + gi3) * D1 + eh * 64 + col] = v3;
        } else {
            *(float2*)&g_msg1[((size_t)c * NN + gi0) * 64 + col] = v0;
            *(float2*)&g_msg1[((size_t)c * NN + gi1) * 64 + col] = v1;
            *(float2*)&g_msg1[((size_t)c * NN + gi2) * 64 + col] = v2;
            *(float2*)&g_msg1[((size_t)c * NN + gi3) * 64 + col] = v3;
        }
    }
}

// partial[b,chunk,h] = sum over eh and 128 n-rows of elu(msg1)
__global__ void k_reduce1() {
    int b = blockIdx.y, ch = blockIdx.x;
    int n0 = ch * 128;
    int h = threadIdx.x & 63, sub = threadIdx.x >> 6;
    float s = 0.f;
#pragma unroll
    for (int eh = 0; eh < EH; eh++) {
        const float* m = g_msg1 + ((size_t)(eh * BB + b) * NN + n0) * 64;
        for (int n = sub; n < 128; n += 4) {
            float x = m[(size_t)n * 64 + h];
            s += x > 0.f ? x : expm1f(x);
        }
    }
    __shared__ float red[256];
    red[threadIdx.x] = s;
    __syncthreads();
    if (threadIdx.x < 64)
        g_partial[(b * 16 + ch) * 64 + threadIdx.x] =
            red[threadIdx.x] + red[64 + threadIdx.x] +
            red[128 + threadIdx.x] + red[192 + threadIdx.x];
}

__global__ void k_out(const float* __restrict__ Wout,
                      const float* __restrict__ bout,
                      float* __restrict__ out) {
    __shared__ float v[BB * 64];
    int t = threadIdx.x;
    {
        int b = t >> 6, h = t & 63;
        float s = 0.f;
#pragma unroll
        for (int p = 0; p < 16; p++) s += g_partial[(b * 16 + p) * 64 + h];
        v[t] = s;
    }
    __syncthreads();
    if (t < 128) {
        int b = t >> 5, o = t & 31;
        float s = 0.f;
#pragma unroll
        for (int hh = 0; hh < 64; hh++) s += v[b * 64 + hh] * Wout[hh * OO + o];
        out[b * OO + o] = s * (1.f / 8192.f) + bout[o];
    }
}

// ---------------- launcher ----------------
extern "C" void kernel_launch(void* const* d_in, const int* in_sizes, int n_in,
                              void* d_out, int out_size) {
    const float* nodes = (const float*)d_in[0];
    const float* edges = (const float*)d_in[1];
    const float* W_emb = (const float*)d_in[2];
    const float* b_emb = (const float*)d_in[3];
    const float* Wf0   = (const float*)d_in[4];
    const float* w1_0  = (const float*)d_in[5];
    const float* b1_0  = (const float*)d_in[6];
    const float* w2_0  = (const float*)d_in[7];
    const float* b2_0  = (const float*)d_in[8];
    const float* bias0 = (const float*)d_in[9];
    const float* Wf1   = (const float*)d_in[10];
    const float* w1_1  = (const float*)d_in[11];
    const float* b1_1  = (const float*)d_in[12];
    const float* w2_1  = (const float*)d_in[13];
    const float* b2_1  = (const float*)d_in[14];
    const float* bias1 = (const float*)d_in[15];
    const float* W_out = (const float*)d_in[16];
    const float* b_out = (const float*)d_in[17];
    float* out = (float*)d_out;

    k_split_edges<<<BNN / 2 / 256, 256>>>(edges);
    k_embed<<<(BB * NN) / 4, 256>>>(nodes, W_emb, b_emb);

    // ---- layer 0 (DIN = 64) ----
    k_wh<64><<<dim3(NN / 64, BB, EH), 128>>>(Wf0, w1_0, b1_0, w2_0, b2_0);
    k_stats<<<dim3(2, 32, 8), 256>>>();
    k_whnT<<<dim3(NN / 64, CC), 256>>>();
    k_msg_mma<0><<<dim3(NN / 128, 8), 256>>>(bias0);

    // ---- layer 1 (DIN = 256) ----
    k_wh<256><<<dim3(NN / 64, BB, EH), 128>>>(Wf1, w1_1, b1_1, w2_1, b2_1);
    k_stats<<<dim3(2, 32, 8), 256>>>();
    k_whnT<<<dim3(NN / 64, CC), 256>>>();
    k_msg_mma<1><<<dim3(NN / 128, 8), 256>>>(bias1);

    // ---- final reduction + output head ----
    k_reduce1<<<dim3(16, BB), 256>>>();
    k_out<<<1, 256>>>(W_out, b_out, out);
}

// round 15
// speedup vs baseline: 1.5911x; 1.0084x over previous
#include <cuda_runtime.h>
#include <cuda_fp16.h>
#include <cstdint>

typedef unsigned long long ull;

// Problem constants
#define BB 4
#define NN 2048
#define II 32
#define HH 64
#define OO 32
#define EE 2
#define HD 2
#define EH 4              // E*HD
#define CC 16             // EH*B combos
#define D1 256            // H*HD*E
#define BNN 16777216      // B*N*N
#define SLAB (NN*NN/2)    // half2 per (e,b) slab

// ---------------- scratch (device globals; no allocation) ----------------
__device__ __align__(16) __half2 g_edgeH2[BNN];   // exp(edge) fp16 [e][b][i][k]
__device__ float g_state0[BB * NN * HH];
__device__ float g_state1[BB * NN * D1];
__device__ float g_Wh [CC * NN * HH];
__device__ __align__(16) __half2 g_WhnT[CC * 64 * 1024];  // [c][d][k/2]
__device__ __align__(16) __half2 g_E1d[CC * NN];  // (exp(a1), exp(a1)) per row i
__device__ __align__(16) __half2 g_F1d[CC * NN];  // (exp(.2 a1), ...)
__device__ __align__(16) __half g_E2h[CC * NN];   // exp(a2 - g) per col k
__device__ __align__(16) __half g_F2h[CC * NN];   // exp(.2 a2 - g)
__device__ float g_spart[32 * CC * NN];
__device__ float g_msg1[CC * NN * HH];
__device__ float g_partial[BB * 16 * HH];

// ---------------- f32x2 packed helpers (Blackwell FFMA2) ----------------
__device__ __forceinline__ ull pk2(float x) {
    ull r;
    asm("mov.b64 %0, {%1, %1};" : "=l"(r) : "f"(x));
    return r;
}
__device__ __forceinline__ void fma2(ull& d, ull a, ull b) {
    asm("fma.rn.f32x2 %0, %1, %2, %0;" : "+l"(d) : "l"(a), "l"(b));
}
__device__ __forceinline__ void upk2(ull v, float& lo, float& hi) {
    asm("mov.b64 {%0, %1}, %2;" : "=f"(lo), "=f"(hi) : "l"(v));
}

// ---------------- HMMA helper: m16n8k16 fp16 -> fp32 ----------------
__device__ __forceinline__ void mma16816(float* d,
                                         uint32_t a0, uint32_t a1,
                                         uint32_t a2, uint32_t a3,
                                         uint32_t b0, uint32_t b1) {
    asm volatile(
        "mma.sync.aligned.m16n8k16.row.col.f32.f16.f16.f32 "
        "{%0,%1,%2,%3}, {%4,%5,%6,%7}, {%8,%9}, {%0,%1,%2,%3};"
        : "+f"(d[0]), "+f"(d[1]), "+f"(d[2]), "+f"(d[3])
        : "r"(a0), "r"(a1), "r"(a2), "r"(a3), "r"(b0), "r"(b1));
}

__device__ __forceinline__ uint32_t h2u(__half2 h) {
    return *reinterpret_cast<uint32_t*>(&h);
}
// P-pair = eE * max(E1*E2, F1*F2)   (exp factorization of lrelu softmax logit)
__device__ __forceinline__ __half2 ppair(__half2 eE, __half2 E1, __half2 F1,
                                         __half2 E2, __half2 F2) {
    return __hmul2(eE, __hmax2(__hmul2(E1, E2), __hmul2(F1, F2)));
}

// ---------------- async copy + ldmatrix helpers ----------------
__device__ __forceinline__ uint32_t smem_u32(const void* p) {
    uint32_t a;
    asm("{ .reg .u64 t; cvta.to.shared.u64 t, %1; cvt.u32.u64 %0, t; }"
        : "=r"(a) : "l"(p));
    return a;
}
__device__ __forceinline__ void cpa16(uint32_t dst, const void* src) {
    asm volatile("cp.async.cg.shared.global [%0], [%1], 16;" :: "r"(dst), "l"(src));
}
#define CP_COMMIT() asm volatile("cp.async.commit_group;" ::: "memory")
#define CP_WAIT1()  asm volatile("cp.async.wait_group 1;" ::: "memory")
#define CP_WAIT0()  asm volatile("cp.async.wait_group 0;" ::: "memory")
__device__ __forceinline__ void ldm_x4(uint32_t& r0, uint32_t& r1,
                                       uint32_t& r2, uint32_t& r3, uint32_t a) {
    asm volatile("ldmatrix.sync.aligned.m8n8.x4.shared.b16 {%0,%1,%2,%3}, [%4];"
        : "=r"(r0), "=r"(r1), "=r"(r2), "=r"(r3) : "r"(a));
}

// ---------------- kernels ----------------

// split interleaved fp32 edges (B,N,N,E) -> two contiguous fp16 exp(edge) slabs.
// exp computed on fp16 pairs via ex2.approx.f16x2 (1 MUFU per 2 elements);
// fp32 source read with evict-first so the fp16 output stays L2-resident.
__global__ void __launch_bounds__(256) k_split_edges(const float4* __restrict__ edges) {
    size_t t = (size_t)blockIdx.x * blockDim.x + threadIdx.x;  // over BNN/4
    float4 v0 = __ldcs(&edges[2 * t]);
    float4 v1 = __ldcs(&edges[2 * t + 1]);
    __half2 h0 = h2exp(__floats2half2_rn(v0.x, v0.z));   // e=0, k pair 0
    __half2 h1 = h2exp(__floats2half2_rn(v1.x, v1.z));   // e=0, k pair 1
    __half2 g0 = h2exp(__floats2half2_rn(v0.y, v0.w));   // e=1
    __half2 g1 = h2exp(__floats2half2_rn(v1.y, v1.w));
    ull he, ge;
    ((__half2*)&he)[0] = h0; ((__half2*)&he)[1] = h1;
    ((__half2*)&ge)[0] = g0; ((__half2*)&ge)[1] = g1;
    *(ull*)&g_edgeH2[2 * t] = he;
    *(ull*)&g_edgeH2[BNN / 2 + 2 * t] = ge;
}

// state0 = nodes @ W_emb + b_emb
__global__ void k_embed(const float* __restrict__ nodes,
                        const float* __restrict__ Wemb,
                        const float* __restrict__ bemb) {
    __shared__ float sW[II * HH];
    int tid = threadIdx.x;
    for (int i = tid; i < II * HH; i += 256) sW[i] = Wemb[i];
    __syncthreads();
    int row = blockIdx.x * 4 + (tid >> 6);
    int h = tid & 63;
    const float* nr = nodes + (size_t)row * II;
    float acc = bemb[h];
#pragma unroll
    for (int d = 0; d < II; d++) acc += __ldg(&nr[d]) * sW[d * HH + h];
    g_state0[(size_t)row * HH + h] = acc;
}

// Wh[eh,b,n,:] = state @ Wf[eh]  (FFMA2 micro-kernel) + FUSED a1/a2 exp tables
template <int DIN>
__global__ void __launch_bounds__(128) k_wh(const float* __restrict__ Wf,
                                            const float* __restrict__ w1,
                                            const float* __restrict__ b1,
                                            const float* __restrict__ w2,
                                            const float* __restrict__ b2) {
    __shared__ float sS[64][66];
    __shared__ __align__(16) float sW[64][68];
    __shared__ float w1s[64], w2s[64];
    const float* src = (DIN == 64) ? g_state0 : g_state1;
    int tid = threadIdx.x;
    int n0 = blockIdx.x * 64;
    int b = blockIdx.y;
    int eh = blockIdx.z;
    const float* Wfe = Wf + (size_t)eh * DIN * 64;
    const float* S = src + ((size_t)b * NN + n0) * DIN;
    int ti = tid >> 3, td = tid & 7;
    int ry = tid >> 1, xs = (tid & 1) * 32;
    if (tid < 64) w1s[tid] = w1[eh * 64 + tid];
    else if (tid < 128) w2s[tid - 64] = w2[eh * 64 + tid - 64];
    ull acc[16];
#pragma unroll
    for (int r = 0; r < 16; r++) acc[r] = 0ULL;

    for (int d0 = 0; d0 < DIN; d0 += 64) {
        __syncthreads();
#pragma unroll
        for (int j = 0; j < 8; j++) {
            float4 v = *(const float4*)&S[(size_t)ry * DIN + d0 + xs + 4 * j];
            sS[ry][xs + 4 * j + 0] = v.x;
            sS[ry][xs + 4 * j + 1] = v.y;
            sS[ry][xs + 4 * j + 2] = v.z;
            sS[ry][xs + 4 * j + 3] = v.w;
        }
#pragma unroll
        for (int j = 0; j < 8; j++)
            *(float4*)&sW[ry][xs + 4 * j] =
                *(const float4*)&Wfe[(size_t)(d0 + ry) * 64 + xs + 4 * j];
        __syncthreads();
#pragma unroll 8
        for (int d = 0; d < 64; d++) {
            const ull* wp = (const ull*)&sW[d][8 * td];
            ull w0 = wp[0], w1v = wp[1], w2v = wp[2], w3 = wp[3];
#pragma unroll
            for (int r = 0; r < 4; r++) {
                ull s = pk2(sS[4 * ti + r][d]);
                fma2(acc[4 * r + 0], s, w0);
                fma2(acc[4 * r + 1], s, w1v);
                fma2(acc[4 * r + 2], s, w2v);
                fma2(acc[4 * r + 3], s, w3);
            }
        }
    }
    int c = eh * BB + b;
    size_t base = (size_t)c * NN + n0;
    float b1v = b1[eh], b2v = b2[eh];
#pragma unroll
    for (int r = 0; r < 4; r++) {
        float o[8];
        upk2(acc[4 * r + 0], o[0], o[1]);
        upk2(acc[4 * r + 1], o[2], o[3]);
        upk2(acc[4 * r + 2], o[4], o[5]);
        upk2(acc[4 * r + 3], o[6], o[7]);
        float* dst = &g_Wh[(base + 4 * ti + r) * 64 + 8 * td];
        *(float4*)dst = make_float4(o[0], o[1], o[2], o[3]);
        *(float4*)(dst + 4) = make_float4(o[4], o[5], o[6], o[7]);
        // fused a1/a2 dot products
        float p1 = 0.f, p2 = 0.f;
#pragma unroll
        for (int j = 0; j < 8; j++) {
            p1 += o[j] * w1s[8 * td + j];
            p2 += o[j] * w2s[8 * td + j];
        }
#pragma unroll
        for (int off = 4; off; off >>= 1) {
            p1 += __shfl_xor_sync(0xffffffffu, p1, off);
            p2 += __shfl_xor_sync(0xffffffffu, p2, off);
        }
        if (td == 0) {
            size_t n = base + 4 * ti + r;
            float a1v = p1 + b1v;
            float a2v = p2 + b2v;
            float E1 = __expf(a1v), F1 = __expf(0.2f * a1v);
            g_E1d[n] = __floats2half2_rn(E1, E1);
            g_F1d[n] = __floats2half2_rn(F1, F1);
            float g = fmaxf(a2v, 0.2f * a2v);
            g_E2h[n] = __float2half_rn(__expf(a2v - g));
            g_F2h[n] = __float2half_rn(__expf(0.2f * a2v - g));
        }
    }
}

// partial s[k]: both heads of an (e,b) slab, 8 k per thread (2x 8B edge loads
// per row -> 2x MLP). grid (ktile=2, ichunk=32, eb=8), 128 threads.
__global__ void __launch_bounds__(128) k_stats() {
    __shared__ __half2 sE1a[64], sF1a[64], sE1b[64], sF1b[64];
    int eb = blockIdx.z;
    int e = eb >> 2, b = eb & 3;
    int c0 = (2 * e) * BB + b, c1 = (2 * e + 1) * BB + b;
    int tid = threadIdx.x;
    int kbase = blockIdx.x * 1024;
    int i0 = blockIdx.y * 64;
    if (tid < 64) {
        sE1a[tid] = g_E1d[c0 * NN + i0 + tid];
        sF1a[tid] = g_F1d[c0 * NN + i0 + tid];
        sE1b[tid] = g_E1d[c1 * NN + i0 + tid];
        sF1b[tid] = g_F1d[c1 * NN + i0 + tid];
    }
    __syncthreads();
    int k = kbase + 8 * tid;
    uint4 E2au = *(const uint4*)&g_E2h[c0 * NN + k];
    uint4 F2au = *(const uint4*)&g_F2h[c0 * NN + k];
    uint4 E2bu = *(const uint4*)&g_E2h[c1 * NN + k];
    uint4 F2bu = *(const uint4*)&g_F2h[c1 * NN + k];
    const __half2* E2a = (const __half2*)&E2au;
    const __half2* F2a = (const __half2*)&F2au;
    const __half2* E2b = (const __half2*)&E2bu;
    const __half2* F2b = (const __half2*)&F2bu;
    const ull* egg = (const ull*)(g_edgeH2 + (size_t)eb * SLAB) +
                     (size_t)i0 * (NN / 4) + (k >> 2);
    float sa[8], sb[8];
#pragma unroll
    for (int q = 0; q < 8; q++) { sa[q] = 0.f; sb[q] = 0.f; }
#pragma unroll 4
    for (int i = 0; i < 64; i++) {
        ull ev0 = egg[(size_t)i * (NN / 4)];
        ull ev1 = egg[(size_t)i * (NN / 4) + 1];
        __half2 ea = sE1a[i], fa = sF1a[i], ebv = sE1b[i], fb = sF1b[i];
#pragma unroll
        for (int q = 0; q < 4; q++) {
            __half2 ev = (q < 2) ? ((__half2*)&ev0)[q] : ((__half2*)&ev1)[q - 2];
            float2 ra = __half22float2(ppair(ev, ea, fa, E2a[q], F2a[q]));
            float2 rb = __half22float2(ppair(ev, ebv, fb, E2b[q], F2b[q]));
            sa[2 * q] += ra.x; sa[2 * q + 1] += ra.y;
            sb[2 * q] += rb.x; sb[2 * q + 1] += rb.y;
        }
    }
    float* spa = &g_spart[((size_t)blockIdx.y * CC + c0) * NN + k];
    float* spb = &g_spart[((size_t)blockIdx.y * CC + c1) * NN + k];
    *(float4*)spa = make_float4(sa[0], sa[1], sa[2], sa[3]);
    *(float4*)(spa + 4) = make_float4(sa[4], sa[5], sa[6], sa[7]);
    *(float4*)spb = make_float4(sb[0], sb[1], sb[2], sb[3]);
    *(float4*)(spb + 4) = make_float4(sb[4], sb[5], sb[6], sb[7]);
}

// WhnT[c][d][k] = (Wh[c][k][d] / s[c][k]) fp16 transposed; s summed inline.
__global__ void __launch_bounds__(256) k_whnT() {
    __shared__ float tl[64][65];
    int c = blockIdx.y;
    int k0 = blockIdx.x * 64;
    int tid = threadIdx.x;
    int ky = tid >> 6, d = tid & 63;
#pragma unroll
    for (int p = 0; p < 16; p++)
        tl[4 * p + ky][d] = g_Wh[((size_t)c * NN + k0 + 4 * p + ky) * 64 + d];
    __syncthreads();
    int lam = tid & 31, dw = tid >> 5;
    float sx = 0.f, sy = 0.f;
#pragma unroll
    for (int ic = 0; ic < 32; ic++) {
        float2 p = *(const float2*)&g_spart[((size_t)ic * CC + c) * NN + k0 + 2 * lam];
        sx += p.x; sy += p.y;
    }
    float rx = __fdividef(1.f, sx), ry = __fdividef(1.f, sy);
#pragma unroll
    for (int q = 0; q < 8; q++) {
        int dd = dw * 8 + q;
        g_WhnT[(size_t)(c * 64 + dd) * 1024 + (k0 >> 1) + lam] =
            __floats2half2_rn(tl[2 * lam][dd] * rx, tl[2 * lam + 1][dd] * ry);
    }
}

// msg via HMMA: D[128 i, 64 d] for BOTH heads of an (e,b) slab.
// 8 warps: warp = (ig, head); each warp covers 32 i-rows x 64 d of its head,
// reusing each B fragment across two A fragments. 3-stage cp.async ring.
// grid (16 i-tiles, 8 eb), 256 threads.
#define BTILE 3072   // 64 rows * 48B pitch
template <int LAYER>
__global__ void __launch_bounds__(256) k_msg_mma(const float* __restrict__ bias) {
    __shared__ __align__(16) char sB[3][2][BTILE];   // [buf][head][row*48]
    int tid = threadIdx.x;
    int w = tid >> 5, lane = tid & 31;
    int grp = lane >> 2, qd = lane & 3;
    int head = w & 1, ig = w >> 1;
    int eb = blockIdx.y;
    int e = eb >> 2, b = eb & 3;
    int c = (2 * e + head) * BB + b;
    int i0 = blockIdx.x * 128;
    int iw = i0 + 32 * ig;

    uint32_t sBb = smem_u32(sB);

    const __half2* eslab = g_edgeH2 + (size_t)eb * SLAB;
    const __half* E2p = g_E2h + c * NN;
    const __half* F2p = g_F2h + c * NN;

    __half2 E1r0 = g_E1d[c * NN + iw + grp];
    __half2 F1r0 = g_F1d[c * NN + iw + grp];
    __half2 E1r1 = g_E1d[c * NN + iw + grp + 8];
    __half2 F1r1 = g_F1d[c * NN + iw + grp + 8];
    __half2 E1r2 = g_E1d[c * NN + iw + grp + 16];
    __half2 F1r2 = g_F1d[c * NN + iw + grp + 16];
    __half2 E1r3 = g_E1d[c * NN + iw + grp + 24];
    __half2 F1r3 = g_F1d[c * NN + iw + grp + 24];

    const __half2* er0 = eslab + (size_t)(iw + grp) * (NN / 2);
    const __half2* er1 = er0 + (size_t)8 * (NN / 2);
    const __half2* er2 = er0 + (size_t)16 * (NN / 2);
    const __half2* er3 = er0 + (size_t)24 * (NN / 2);

    // staging: 256 threads -> one 16B cp.async each per tile
    int sd = tid >> 2, shh = (tid >> 1) & 1, sp = tid & 1;
    uint32_t sdst = sBb + shh * BTILE + sd * 48 + sp * 16;
    const __half2* ssrc = g_WhnT + (size_t)((2 * e + shh) * BB + b) * 64 * 1024 +
                          (size_t)sd * 1024 + 4 * sp;

    // ldmatrix lane address
    int m = lane >> 3, rr = lane & 7;
    uint32_t lmLane = (uint32_t)((8 * (m >> 1) + rr) * 48 + (m & 1) * 16) + head * BTILE;

    float accA[8][4], accB[8][4];
#pragma unroll
    for (int nt = 0; nt < 8; nt++)
#pragma unroll
        for (int j = 0; j < 4; j++) { accA[nt][j] = 0.f; accB[nt][j] = 0.f; }

    // prologue: stage tile 0 into buf 0
    cpa16(sdst, ssrc);
    CP_COMMIT();

    // edge register prefetch (t = 0)
    __half2 p0a = er0[qd], p0b = er0[qd + 4];
    __half2 p1a = er1[qd], p1b = er1[qd + 4];
    __half2 p2a = er2[qd], p2b = er2[qd + 4];
    __half2 p3a = er3[qd], p3b = er3[qd + 4];

    for (int t = 0; t < 128; t++) {
        int buf = t - (t / 3) * 3;      // t % 3
        int kh = 8 * t;
        __half2 c0a = p0a, c0b = p0b, c1a = p1a, c1b = p1b;
        __half2 c2a = p2a, c2b = p2b, c3a = p3a, c3b = p3b;
        if (t < 127) {
            p0a = er0[kh + 8 + qd]; p0b = er0[kh + 8 + qd + 4];
            p1a = er1[kh + 8 + qd]; p1b = er1[kh + 8 + qd + 4];
            p2a = er2[kh + 8 + qd]; p2b = er2[kh + 8 + qd + 4];
            p3a = er3[kh + 8 + qd]; p3b = er3[kh + 8 + qd + 4];
            int nbuf = (t + 1) - ((t + 1) / 3) * 3;
            cpa16(sdst + nbuf * (2 * BTILE), ssrc + kh + 8);
            CP_COMMIT();
            CP_WAIT1();
        } else {
            CP_WAIT0();
        }
        __syncthreads();   // tile t staged & prior ldmatrix of this buf drained

        __half2 E2a = *(const __half2*)&E2p[16 * t + 2 * qd];
        __half2 F2a = *(const __half2*)&F2p[16 * t + 2 * qd];
        __half2 E2b = *(const __half2*)&E2p[16 * t + 2 * qd + 8];
        __half2 F2b = *(const __half2*)&F2p[16 * t + 2 * qd + 8];

        uint32_t A0 = h2u(ppair(c0a, E1r0, F1r0, E2a, F2a));
        uint32_t A1 = h2u(ppair(c1a, E1r1, F1r1, E2a, F2a));
        uint32_t A2 = h2u(ppair(c0b, E1r0, F1r0, E2b, F2b));
        uint32_t A3 = h2u(ppair(c1b, E1r1, F1r1, E2b, F2b));
        uint32_t A4 = h2u(ppair(c2a, E1r2, F1r2, E2a, F2a));
        uint32_t A5 = h2u(ppair(c3a, E1r3, F1r3, E2a, F2a));
        uint32_t A6 = h2u(ppair(c2b, E1r2, F1r2, E2b, F2b));
        uint32_t A7 = h2u(ppair(c3b, E1r3, F1r3, E2b, F2b));

        // B fragments for this warp's head only
        uint32_t Bf[8][2];
        uint32_t tb = sBb + buf * (2 * BTILE) + lmLane;
#pragma unroll
        for (int j = 0; j < 4; j++)
            ldm_x4(Bf[2 * j][0], Bf[2 * j][1],
                   Bf[2 * j + 1][0], Bf[2 * j + 1][1], tb + j * 768);

#pragma unroll
        for (int nt = 0; nt < 8; nt++) {
            mma16816(accA[nt], A0, A1, A2, A3, Bf[nt][0], Bf[nt][1]);
            mma16816(accB[nt], A4, A5, A6, A7, Bf[nt][0], Bf[nt][1]);
        }
    }

    int gi0 = iw + grp, gi1 = iw + grp + 8;
    int gi2 = iw + grp + 16, gi3 = iw + grp + 24;
    int eh = 2 * e + head;
#pragma unroll
    for (int nt = 0; nt < 8; nt++) {
        int col = 8 * nt + 2 * qd;
        float bx = bias[head * 64 + col], by = bias[head * 64 + col + 1];
        float2 v0 = make_float2(accA[nt][0] + bx, accA[nt][1] + by);
        float2 v1 = make_float2(accA[nt][2] + bx, accA[nt][3] + by);
        float2 v2 = make_float2(accB[nt][0] + bx, accB[nt][1] + by);
        float2 v3 = make_float2(accB[nt][2] + bx, accB[nt][3] + by);
        if (LAYER == 0) {
            *(float2*)&g_state1[((size_t)b * NN + gi0) * D1 + eh * 64 + col] = v0;
            *(float2*)&g_state1[((size_t)b * NN + gi1) * D1 + eh * 64 + col] = v1;
            *(float2*)&g_state1[((size_t)b * NN + gi2) * D1 + eh * 64 + col] = v2;
            *(float2*)&g_state1[((size_t)b * NN + gi3) * D1 + eh * 64 + col] = v3;
        } else {
            *(float2*)&g_msg1[((size_t)c * NN + gi0) * 64 + col] = v0;
            *(float2*)&g_msg1[((size_t)c * NN + gi1) * 64 + col] = v1;
            *(float2*)&g_msg1[((size_t)c * NN + gi2) * 64 + col] = v2;
            *(float2*)&g_msg1[((size_t)c * NN + gi3) * 64 + col] = v3;
        }
    }
}

// partial[b,chunk,h] = sum over eh and 128 n-rows of elu(msg1)
__global__ void k_reduce1() {
    int b = blockIdx.y, ch = blockIdx.x;
    int n0 = ch * 128;
    int h = threadIdx.x & 63, sub = threadIdx.x >> 6;
    float s = 0.f;
#pragma unroll
    for (int eh = 0; eh < EH; eh++) {
        const float* m = g_msg1 + ((size_t)(eh * BB + b) * NN + n0) * 64;
        for (int n = sub; n < 128; n += 4) {
            float x = m[(size_t)n * 64 + h];
            s += x > 0.f ? x : expm1f(x);
        }
    }
    __shared__ float red[256];
    red[threadIdx.x] = s;
    __syncthreads();
    if (threadIdx.x < 64)
        g_partial[(b * 16 + ch) * 64 + threadIdx.x] =
            red[threadIdx.x] + red[64 + threadIdx.x] +
            red[128 + threadIdx.x] + red[192 + threadIdx.x];
}

__global__ void k_out(const float* __restrict__ Wout,
                      const float* __restrict__ bout,
                      float* __restrict__ out) {
    __shared__ float v[BB * 64];
    int t = threadIdx.x;
    {
        int b = t >> 6, h = t & 63;
        float s = 0.f;
#pragma unroll
        for (int p = 0; p < 16; p++) s += g_partial[(b * 16 + p) * 64 + h];
        v[t] = s;
    }
    __syncthreads();
    if (t < 128) {
        int b = t >> 5, o = t & 31;
        float s = 0.f;
#pragma unroll
        for (int hh = 0; hh < 64; hh++) s += v[b * 64 + hh] * Wout[hh * OO + o];
        out[b * OO + o] = s * (1.f / 8192.f) + bout[o];
    }
}

// ---------------- launcher ----------------
extern "C" void kernel_launch(void* const* d_in, const int* in_sizes, int n_in,
                              void* d_out, int out_size) {
    const float* nodes = (const float*)d_in[0];
    const float* edges = (const float*)d_in[1];
    const float* W_emb = (const float*)d_in[2];
    const float* b_emb = (const float*)d_in[3];
    const float* Wf0   = (const float*)d_in[4];
    const float* w1_0  = (const float*)d_in[5];
    const float* b1_0  = (const float*)d_in[6];
    const float* w2_0  = (const float*)d_in[7];
    const float* b2_0  = (const float*)d_in[8];
    const float* bias0 = (const float*)d_in[9];
    const float* Wf1   = (const float*)d_in[10];
    const float* w1_1  = (const float*)d_in[11];
    const float* b1_1  = (const float*)d_in[12];
    const float* w2_1  = (const float*)d_in[13];
    const float* b2_1  = (const float*)d_in[14];
    const float* bias1 = (const float*)d_in[15];
    const float* W_out = (const float*)d_in[16];
    const float* b_out = (const float*)d_in[17];
    float* out = (float*)d_out;

    k_split_edges<<<BNN / 4 / 256, 256>>>((const float4*)edges);
    k_embed<<<(BB * NN) / 4, 256>>>(nodes, W_emb, b_emb);

    // ---- layer 0 (DIN = 64) ----
    k_wh<64><<<dim3(NN / 64, BB, EH), 128>>>(Wf0, w1_0, b1_0, w2_0, b2_0);
    k_stats<<<dim3(2, 32, 8), 128>>>();
    k_whnT<<<dim3(NN / 64, CC), 256>>>();
    k_msg_mma<0><<<dim3(NN / 128, 8), 256>>>(bias0);

    // ---- layer 1 (DIN = 256) ----
    k_wh<256><<<dim3(NN / 64, BB, EH), 128>>>(Wf1, w1_1, b1_1, w2_1, b2_1);
    k_stats<<<dim3(2, 32, 8), 128>>>();
    k_whnT<<<dim3(NN / 64, CC), 256>>>();
    k_msg_mma<1><<<dim3(NN / 128, 8), 256>>>(bias1);

    // ---- final reduction + output head ----
    k_reduce1<<<dim3(16, BB), 256>>>();
    k_out<<<1, 256>>>(W_out, b_out, out);
}

// round 16
// speedup vs baseline: 1.8058x; 1.1350x over previous
#include <cuda_runtime.h>
#include <cuda_fp16.h>
#include <cstdint>

typedef unsigned long long ull;

// Problem constants
#define BB 4
#define NN 2048
#define II 32
#define HH 64
#define OO 32
#define EE 2
#define HD 2
#define EH 4              // E*HD
#define CC 16             // EH*B combos
#define D1 256            // H*HD*E
#define BNN 16777216      // B*N*N
#define SLAB (NN*NN/2)    // half2 per (e,b) slab

// ---------------- scratch (device globals; no allocation) ----------------
__device__ __align__(16) __half2 g_edgeH2[BNN];   // exp(edge) fp16 [e][b][i][k]
__device__ float g_state0[BB * NN * HH];
__device__ float g_state1[BB * NN * D1];
__device__ float g_Wh [CC * NN * HH];
__device__ __align__(16) __half2 g_WhnT[CC * 64 * 1024];  // [c][d][k/2]
__device__ __align__(16) __half2 g_E1d[CC * NN];  // (exp(a1), exp(a1)) per row i
__device__ __align__(16) __half2 g_F1d[CC * NN];  // (exp(.2 a1), ...)
__device__ __align__(16) __half g_E2h[CC * NN];   // exp(a2 - g) per col k
__device__ __align__(16) __half g_F2h[CC * NN];   // exp(.2 a2 - g)
__device__ float g_spart[64 * CC * NN];           // 64 i-chunk partials
__device__ float g_msgp[2 * CC * NN * HH];        // k-half partial msgs
__device__ float g_msg1[CC * NN * HH];
__device__ float g_partial[BB * 16 * HH];

// ---------------- f32x2 packed helpers (Blackwell FFMA2) ----------------
__device__ __forceinline__ ull pk2(float x) {
    ull r;
    asm("mov.b64 %0, {%1, %1};" : "=l"(r) : "f"(x));
    return r;
}
__device__ __forceinline__ void fma2(ull& d, ull a, ull b) {
    asm("fma.rn.f32x2 %0, %1, %2, %0;" : "+l"(d) : "l"(a), "l"(b));
}
__device__ __forceinline__ void upk2(ull v, float& lo, float& hi) {
    asm("mov.b64 {%0, %1}, %2;" : "=f"(lo), "=f"(hi) : "l"(v));
}

// ---------------- HMMA helper: m16n8k16 fp16 -> fp32 ----------------
__device__ __forceinline__ void mma16816(float* d,
                                         uint32_t a0, uint32_t a1,
                                         uint32_t a2, uint32_t a3,
                                         uint32_t b0, uint32_t b1) {
    asm volatile(
        "mma.sync.aligned.m16n8k16.row.col.f32.f16.f16.f32 "
        "{%0,%1,%2,%3}, {%4,%5,%6,%7}, {%8,%9}, {%0,%1,%2,%3};"
        : "+f"(d[0]), "+f"(d[1]), "+f"(d[2]), "+f"(d[3])
        : "r"(a0), "r"(a1), "r"(a2), "r"(a3), "r"(b0), "r"(b1));
}

__device__ __forceinline__ uint32_t h2u(__half2 h) {
    return *reinterpret_cast<uint32_t*>(&h);
}
// P-pair = eE * max(E1*E2, F1*F2)   (exp factorization of lrelu softmax logit)
__device__ __forceinline__ __half2 ppair(__half2 eE, __half2 E1, __half2 F1,
                                         __half2 E2, __half2 F2) {
    return __hmul2(eE, __hmax2(__hmul2(E1, E2), __hmul2(F1, F2)));
}

// ---------------- async copy + ldmatrix helpers ----------------
__device__ __forceinline__ uint32_t smem_u32(const void* p) {
    uint32_t a;
    asm("{ .reg .u64 t; cvta.to.shared.u64 t, %1; cvt.u32.u64 %0, t; }"
        : "=r"(a) : "l"(p));
    return a;
}
__device__ __forceinline__ void cpa16(uint32_t dst, const void* src) {
    asm volatile("cp.async.cg.shared.global [%0], [%1], 16;" :: "r"(dst), "l"(src));
}
#define CP_COMMIT() asm volatile("cp.async.commit_group;" ::: "memory")
#define CP_WAIT1()  asm volatile("cp.async.wait_group 1;" ::: "memory")
#define CP_WAIT0()  asm volatile("cp.async.wait_group 0;" ::: "memory")
__device__ __forceinline__ void ldm_x4(uint32_t& r0, uint32_t& r1,
                                       uint32_t& r2, uint32_t& r3, uint32_t a) {
    asm volatile("ldmatrix.sync.aligned.m8n8.x4.shared.b16 {%0,%1,%2,%3}, [%4];"
        : "=r"(r0), "=r"(r1), "=r"(r2), "=r"(r3) : "r"(a));
}

// ---------------- kernels ----------------

// split interleaved fp32 edges (B,N,N,E) -> two contiguous fp16 exp(edge) slabs.
__global__ void __launch_bounds__(256) k_split_edges(const float4* __restrict__ edges) {
    size_t t = (size_t)blockIdx.x * blockDim.x + threadIdx.x;  // over BNN/4
    float4 v0 = __ldcs(&edges[2 * t]);
    float4 v1 = __ldcs(&edges[2 * t + 1]);
    __half2 h0 = h2exp(__floats2half2_rn(v0.x, v0.z));   // e=0, k pair 0
    __half2 h1 = h2exp(__floats2half2_rn(v1.x, v1.z));   // e=0, k pair 1
    __half2 g0 = h2exp(__floats2half2_rn(v0.y, v0.w));   // e=1
    __half2 g1 = h2exp(__floats2half2_rn(v1.y, v1.w));
    ull he, ge;
    ((__half2*)&he)[0] = h0; ((__half2*)&he)[1] = h1;
    ((__half2*)&ge)[0] = g0; ((__half2*)&ge)[1] = g1;
    *(ull*)&g_edgeH2[2 * t] = he;
    *(ull*)&g_edgeH2[BNN / 2 + 2 * t] = ge;
}

// state0 = nodes @ W_emb + b_emb
__global__ void k_embed(const float* __restrict__ nodes,
                        const float* __restrict__ Wemb,
                        const float* __restrict__ bemb) {
    __shared__ float sW[II * HH];
    int tid = threadIdx.x;
    for (int i = tid; i < II * HH; i += 256) sW[i] = Wemb[i];
    __syncthreads();
    int row = blockIdx.x * 4 + (tid >> 6);
    int h = tid & 63;
    const float* nr = nodes + (size_t)row * II;
    float acc = bemb[h];
#pragma unroll
    for (int d = 0; d < II; d++) acc += __ldg(&nr[d]) * sW[d * HH + h];
    g_state0[(size_t)row * HH + h] = acc;
}

// Wh[eh,b,n,:] = state @ Wf[eh]  (FFMA2 micro-kernel) + FUSED a1/a2 exp tables
template <int DIN>
__global__ void __launch_bounds__(128) k_wh(const float* __restrict__ Wf,
                                            const float* __restrict__ w1,
                                            const float* __restrict__ b1,
                                            const float* __restrict__ w2,
                                            const float* __restrict__ b2) {
    __shared__ float sS[64][66];
    __shared__ __align__(16) float sW[64][68];
    __shared__ float w1s[64], w2s[64];
    const float* src = (DIN == 64) ? g_state0 : g_state1;
    int tid = threadIdx.x;
    int n0 = blockIdx.x * 64;
    int b = blockIdx.y;
    int eh = blockIdx.z;
    const float* Wfe = Wf + (size_t)eh * DIN * 64;
    const float* S = src + ((size_t)b * NN + n0) * DIN;
    int ti = tid >> 3, td = tid & 7;
    int ry = tid >> 1, xs = (tid & 1) * 32;
    if (tid < 64) w1s[tid] = w1[eh * 64 + tid];
    else if (tid < 128) w2s[tid - 64] = w2[eh * 64 + tid - 64];
    ull acc[16];
#pragma unroll
    for (int r = 0; r < 16; r++) acc[r] = 0ULL;

    for (int d0 = 0; d0 < DIN; d0 += 64) {
        __syncthreads();
#pragma unroll
        for (int j = 0; j < 8; j++) {
            float4 v = *(const float4*)&S[(size_t)ry * DIN + d0 + xs + 4 * j];
            sS[ry][xs + 4 * j + 0] = v.x;
            sS[ry][xs + 4 * j + 1] = v.y;
            sS[ry][xs + 4 * j + 2] = v.z;
            sS[ry][xs + 4 * j + 3] = v.w;
        }
#pragma unroll
        for (int j = 0; j < 8; j++)
            *(float4*)&sW[ry][xs + 4 * j] =
                *(const float4*)&Wfe[(size_t)(d0 + ry) * 64 + xs + 4 * j];
        __syncthreads();
#pragma unroll 8
        for (int d = 0; d < 64; d++) {
            const ull* wp = (const ull*)&sW[d][8 * td];
            ull w0 = wp[0], w1v = wp[1], w2v = wp[2], w3 = wp[3];
#pragma unroll
            for (int r = 0; r < 4; r++) {
                ull s = pk2(sS[4 * ti + r][d]);
                fma2(acc[4 * r + 0], s, w0);
                fma2(acc[4 * r + 1], s, w1v);
                fma2(acc[4 * r + 2], s, w2v);
                fma2(acc[4 * r + 3], s, w3);
            }
        }
    }
    int c = eh * BB + b;
    size_t base = (size_t)c * NN + n0;
    float b1v = b1[eh], b2v = b2[eh];
#pragma unroll
    for (int r = 0; r < 4; r++) {
        float o[8];
        upk2(acc[4 * r + 0], o[0], o[1]);
        upk2(acc[4 * r + 1], o[2], o[3]);
        upk2(acc[4 * r + 2], o[4], o[5]);
        upk2(acc[4 * r + 3], o[6], o[7]);
        float* dst = &g_Wh[(base + 4 * ti + r) * 64 + 8 * td];
        *(float4*)dst = make_float4(o[0], o[1], o[2], o[3]);
        *(float4*)(dst + 4) = make_float4(o[4], o[5], o[6], o[7]);
        // fused a1/a2 dot products
        float p1 = 0.f, p2 = 0.f;
#pragma unroll
        for (int j = 0; j < 8; j++) {
            p1 += o[j] * w1s[8 * td + j];
            p2 += o[j] * w2s[8 * td + j];
        }
#pragma unroll
        for (int off = 4; off; off >>= 1) {
            p1 += __shfl_xor_sync(0xffffffffu, p1, off);
            p2 += __shfl_xor_sync(0xffffffffu, p2, off);
        }
        if (td == 0) {
            size_t n = base + 4 * ti + r;
            float a1v = p1 + b1v;
            float a2v = p2 + b2v;
            float E1 = __expf(a1v), F1 = __expf(0.2f * a1v);
            g_E1d[n] = __floats2half2_rn(E1, E1);
            g_F1d[n] = __floats2half2_rn(F1, F1);
            float g = fmaxf(a2v, 0.2f * a2v);
            g_E2h[n] = __float2half_rn(__expf(a2v - g));
            g_F2h[n] = __float2half_rn(__expf(0.2f * a2v - g));
        }
    }
}

// partial s[k]: both heads of an (e,b) slab, 4 k per thread, 32 i-rows.
// grid (ktile=2, ichunk=64, eb=8) = 1024 blocks, 256 threads (86% occ ceiling).
__global__ void __launch_bounds__(256) k_stats() {
    __shared__ __half2 sE1a[32], sF1a[32], sE1b[32], sF1b[32];
    int eb = blockIdx.z;
    int e = eb >> 2, b = eb & 3;
    int c0 = (2 * e) * BB + b, c1 = (2 * e + 1) * BB + b;
    int tid = threadIdx.x;
    int kbase = blockIdx.x * 1024;
    int i0 = blockIdx.y * 32;
    if (tid < 32) {
        sE1a[tid] = g_E1d[c0 * NN + i0 + tid];
        sF1a[tid] = g_F1d[c0 * NN + i0 + tid];
        sE1b[tid] = g_E1d[c1 * NN + i0 + tid];
        sF1b[tid] = g_F1d[c1 * NN + i0 + tid];
    }
    __syncthreads();
    int k = kbase + 4 * tid;
    __half2 E2a0, E2a1, F2a0, F2a1, E2b0, E2b1, F2b0, F2b1;
    { ull v = *(const ull*)&g_E2h[c0 * NN + k];
      E2a0 = ((__half2*)&v)[0]; E2a1 = ((__half2*)&v)[1]; }
    { ull v = *(const ull*)&g_F2h[c0 * NN + k];
      F2a0 = ((__half2*)&v)[0]; F2a1 = ((__half2*)&v)[1]; }
    { ull v = *(const ull*)&g_E2h[c1 * NN + k];
      E2b0 = ((__half2*)&v)[0]; E2b1 = ((__half2*)&v)[1]; }
    { ull v = *(const ull*)&g_F2h[c1 * NN + k];
      F2b0 = ((__half2*)&v)[0]; F2b1 = ((__half2*)&v)[1]; }
    const ull* egg = (const ull*)(g_edgeH2 + (size_t)eb * SLAB) +
                     (size_t)i0 * (NN / 4) + (k >> 2);
    float s0a = 0.f, s1a = 0.f, s2a = 0.f, s3a = 0.f;
    float s0b = 0.f, s1b = 0.f, s2b = 0.f, s3b = 0.f;
#pragma unroll 8
    for (int i = 0; i < 32; i++) {
        ull ev = egg[(size_t)i * (NN / 4)];
        __half2 e0 = ((__half2*)&ev)[0], e1 = ((__half2*)&ev)[1];
        __half2 ea = sE1a[i], fa = sF1a[i], ebv = sE1b[i], fb = sF1b[i];
        float2 a0 = __half22float2(ppair(e0, ea, fa, E2a0, F2a0));
        float2 a1 = __half22float2(ppair(e1, ea, fa, E2a1, F2a1));
        float2 b0 = __half22float2(ppair(e0, ebv, fb, E2b0, F2b0));
        float2 b1 = __half22float2(ppair(e1, ebv, fb, E2b1, F2b1));
        s0a += a0.x; s1a += a0.y; s2a += a1.x; s3a += a1.y;
        s0b += b0.x; s1b += b0.y; s2b += b1.x; s3b += b1.y;
    }
    *(float4*)&g_spart[((size_t)blockIdx.y * CC + c0) * NN + k] =
        make_float4(s0a, s1a, s2a, s3a);
    *(float4*)&g_spart[((size_t)blockIdx.y * CC + c1) * NN + k] =
        make_float4(s0b, s1b, s2b, s3b);
}

// WhnT[c][d][k] = (Wh[c][k][d] / s[c][k]) fp16 transposed; s summed inline.
__global__ void __launch_bounds__(256) k_whnT() {
    __shared__ float tl[64][65];
    int c = blockIdx.y;
    int k0 = blockIdx.x * 64;
    int tid = threadIdx.x;
    int ky = tid >> 6, d = tid & 63;
#pragma unroll
    for (int p = 0; p < 16; p++)
        tl[4 * p + ky][d] = g_Wh[((size_t)c * NN + k0 + 4 * p + ky) * 64 + d];
    __syncthreads();
    int lam = tid & 31, dw = tid >> 5;
    float sx = 0.f, sy = 0.f;
#pragma unroll
    for (int ic = 0; ic < 64; ic++) {
        float2 p = *(const float2*)&g_spart[((size_t)ic * CC + c) * NN + k0 + 2 * lam];
        sx += p.x; sy += p.y;
    }
    float rx = __fdividef(1.f, sx), ry = __fdividef(1.f, sy);
#pragma unroll
    for (int q = 0; q < 8; q++) {
        int dd = dw * 8 + q;
        g_WhnT[(size_t)(c * 64 + dd) * 1024 + (k0 >> 1) + lam] =
            __floats2half2_rn(tl[2 * lam][dd] * rx, tl[2 * lam + 1][dd] * ry);
    }
}

// msg via HMMA, K split in half across blocks for occupancy.
// grid (16 i-tiles, 8 eb, 2 khalf) = 256 blocks, 256 threads.
// Each block: D_partial[128 i, 64 d] for both heads over its 1024-k half,
// written raw to g_msgp[khalf]; combiner adds halves + bias.
#define BTILE 3072   // 64 rows * 48B pitch
__global__ void __launch_bounds__(256) k_msg_mma() {
    __shared__ __align__(16) char sB[3][2][BTILE];   // [buf][head][row*48]
    int tid = threadIdx.x;
    int w = tid >> 5, lane = tid & 31;
    int grp = lane >> 2, qd = lane & 3;
    int head = w & 1, ig = w >> 1;
    int eb = blockIdx.y;
    int khalf = blockIdx.z;
    int khh = khalf * 512;          // half2 offset of this k-half
    int e = eb >> 2, b = eb & 3;
    int c = (2 * e + head) * BB + b;
    int i0 = blockIdx.x * 128;
    int iw = i0 + 32 * ig;

    uint32_t sBb = smem_u32(sB);

    const __half2* eslab = g_edgeH2 + (size_t)eb * SLAB;
    const __half* E2p = g_E2h + c * NN + khalf * 1024;
    const __half* F2p = g_F2h + c * NN + khalf * 1024;

    __half2 E1r0 = g_E1d[c * NN + iw + grp];
    __half2 F1r0 = g_F1d[c * NN + iw + grp];
    __half2 E1r1 = g_E1d[c * NN + iw + grp + 8];
    __half2 F1r1 = g_F1d[c * NN + iw + grp + 8];
    __half2 E1r2 = g_E1d[c * NN + iw + grp + 16];
    __half2 F1r2 = g_F1d[c * NN + iw + grp + 16];
    __half2 E1r3 = g_E1d[c * NN + iw + grp + 24];
    __half2 F1r3 = g_F1d[c * NN + iw + grp + 24];

    const __half2* er0 = eslab + (size_t)(iw + grp) * (NN / 2) + khh;
    const __half2* er1 = er0 + (size_t)8 * (NN / 2);
    const __half2* er2 = er0 + (size_t)16 * (NN / 2);
    const __half2* er3 = er0 + (size_t)24 * (NN / 2);

    // staging: 256 threads -> one 16B cp.async each per tile
    int sd = tid >> 2, shh = (tid >> 1) & 1, sp = tid & 1;
    uint32_t sdst = sBb + shh * BTILE + sd * 48 + sp * 16;
    const __half2* ssrc = g_WhnT + (size_t)((2 * e + shh) * BB + b) * 64 * 1024 +
                          (size_t)sd * 1024 + 4 * sp + khh;

    // ldmatrix lane address
    int m = lane >> 3, rr = lane & 7;
    uint32_t lmLane = (uint32_t)((8 * (m >> 1) + rr) * 48 + (m & 1) * 16) + head * BTILE;

    float accA[8][4], accB[8][4];
#pragma unroll
    for (int nt = 0; nt < 8; nt++)
#pragma unroll
        for (int j = 0; j < 4; j++) { accA[nt][j] = 0.f; accB[nt][j] = 0.f; }

    // prologue: stage tile 0 into buf 0
    cpa16(sdst, ssrc);
    CP_COMMIT();

    // edge register prefetch (t = 0)
    __half2 p0a = er0[qd], p0b = er0[qd + 4];
    __half2 p1a = er1[qd], p1b = er1[qd + 4];
    __half2 p2a = er2[qd], p2b = er2[qd + 4];
    __half2 p3a = er3[qd], p3b = er3[qd + 4];

    for (int t = 0; t < 64; t++) {
        int buf = t - (t / 3) * 3;      // t % 3
        int kh = 8 * t;
        __half2 c0a = p0a, c0b = p0b, c1a = p1a, c1b = p1b;
        __half2 c2a = p2a, c2b = p2b, c3a = p3a, c3b = p3b;
        if (t < 63) {
            p0a = er0[kh + 8 + qd]; p0b = er0[kh + 8 + qd + 4];
            p1a = er1[kh + 8 + qd]; p1b = er1[kh + 8 + qd + 4];
            p2a = er2[kh + 8 + qd]; p2b = er2[kh + 8 + qd + 4];
            p3a = er3[kh + 8 + qd]; p3b = er3[kh + 8 + qd + 4];
            int nbuf = (t + 1) - ((t + 1) / 3) * 3;
            cpa16(sdst + nbuf * (2 * BTILE), ssrc + kh + 8);
            CP_COMMIT();
            CP_WAIT1();
        } else {
            CP_WAIT0();
        }
        __syncthreads();   // tile t staged & prior ldmatrix of this buf drained

        __half2 E2a = *(const __half2*)&E2p[16 * t + 2 * qd];
        __half2 F2a = *(const __half2*)&F2p[16 * t + 2 * qd];
        __half2 E2b = *(const __half2*)&E2p[16 * t + 2 * qd + 8];
        __half2 F2b = *(const __half2*)&F2p[16 * t + 2 * qd + 8];

        uint32_t A0 = h2u(ppair(c0a, E1r0, F1r0, E2a, F2a));
        uint32_t A1 = h2u(ppair(c1a, E1r1, F1r1, E2a, F2a));
        uint32_t A2 = h2u(ppair(c0b, E1r0, F1r0, E2b, F2b));
        uint32_t A3 = h2u(ppair(c1b, E1r1, F1r1, E2b, F2b));
        uint32_t A4 = h2u(ppair(c2a, E1r2, F1r2, E2a, F2a));
        uint32_t A5 = h2u(ppair(c3a, E1r3, F1r3, E2a, F2a));
        uint32_t A6 = h2u(ppair(c2b, E1r2, F1r2, E2b, F2b));
        uint32_t A7 = h2u(ppair(c3b, E1r3, F1r3, E2b, F2b));

        // B fragments for this warp's head only
        uint32_t Bf[8][2];
        uint32_t tb = sBb + buf * (2 * BTILE) + lmLane;
#pragma unroll
        for (int j = 0; j < 4; j++)
            ldm_x4(Bf[2 * j][0], Bf[2 * j][1],
                   Bf[2 * j + 1][0], Bf[2 * j + 1][1], tb + j * 768);

#pragma unroll
        for (int nt = 0; nt < 8; nt++) {
            mma16816(accA[nt], A0, A1, A2, A3, Bf[nt][0], Bf[nt][1]);
            mma16816(accB[nt], A4, A5, A6, A7, Bf[nt][0], Bf[nt][1]);
        }
    }

    int gi0 = iw + grp, gi1 = iw + grp + 8;
    int gi2 = iw + grp + 16, gi3 = iw + grp + 24;
    float* mp = g_msgp + (size_t)khalf * (CC * NN * 64);
#pragma unroll
    for (int nt = 0; nt < 8; nt++) {
        int col = 8 * nt + 2 * qd;
        *(float2*)&mp[((size_t)c * NN + gi0) * 64 + col] = make_float2(accA[nt][0], accA[nt][1]);
        *(float2*)&mp[((size_t)c * NN + gi1) * 64 + col] = make_float2(accA[nt][2], accA[nt][3]);
        *(float2*)&mp[((size_t)c * NN + gi2) * 64 + col] = make_float2(accB[nt][0], accB[nt][1]);
        *(float2*)&mp[((size_t)c * NN + gi3) * 64 + col] = make_float2(accB[nt][2], accB[nt][3]);
    }
}

// combine the two k-half partials + bias -> state1 (L0) or msg1 (L1)
template <int LAYER>
__global__ void __launch_bounds__(256) k_comb(const float* __restrict__ bias) {
    int idx = blockIdx.x * 256 + threadIdx.x;   // over CC*NN*64/4
    int e4 = idx * 4;
    float4 p0 = *(const float4*)&g_msgp[e4];
    float4 p1 = *(const float4*)&g_msgp[(size_t)(CC * NN * 64) + e4];
    int c = e4 >> 17;
    int rem = e4 & ((1 << 17) - 1);
    int n = rem >> 6, d = rem & 63;
    int eh = c >> 2, b = c & 3;
    int head = eh & 1;
    float4 bv = *(const float4*)&bias[head * 64 + d];
    float4 v = make_float4(p0.x + p1.x + bv.x, p0.y + p1.y + bv.y,
                           p0.z + p1.z + bv.z, p0.w + p1.w + bv.w);
    if (LAYER == 0)
        *(float4*)&g_state1[((size_t)b * NN + n) * D1 + eh * 64 + d] = v;
    else
        *(float4*)&g_msg1[e4] = v;
}

// partial[b,chunk,h] = sum over eh and 128 n-rows of elu(msg1)
__global__ void k_reduce1() {
    int b = blockIdx.y, ch = blockIdx.x;
    int n0 = ch * 128;
    int h = threadIdx.x & 63, sub = threadIdx.x >> 6;
    float s = 0.f;
#pragma unroll
    for (int eh = 0; eh < EH; eh++) {
        const float* m = g_msg1 + ((size_t)(eh * BB + b) * NN + n0) * 64;
        for (int n = sub; n < 128; n += 4) {
            float x = m[(size_t)n * 64 + h];
            s += x > 0.f ? x : expm1f(x);
        }
    }
    __shared__ float red[256];
    red[threadIdx.x] = s;
    __syncthreads();
    if (threadIdx.x < 64)
        g_partial[(b * 16 + ch) * 64 + threadIdx.x] =
            red[threadIdx.x] + red[64 + threadIdx.x] +
            red[128 + threadIdx.x] + red[192 + threadIdx.x];
}

__global__ void k_out(const float* __restrict__ Wout,
                      const float* __restrict__ bout,
                      float* __restrict__ out) {
    __shared__ float v[BB * 64];
    int t = threadIdx.x;
    {
        int b = t >> 6, h = t & 63;
        float s = 0.f;
#pragma unroll
        for (int p = 0; p < 16; p++) s += g_partial[(b * 16 + p) * 64 + h];
        v[t] = s;
    }
    __syncthreads();
    if (t < 128) {
        int b = t >> 5, o = t & 31;
        float s = 0.f;
#pragma unroll
        for (int hh = 0; hh < 64; hh++) s += v[b * 64 + hh] * Wout[hh * OO + o];
        out[b * OO + o] = s * (1.f / 8192.f) + bout[o];
    }
}

// ---------------- launcher ----------------
extern "C" void kernel_launch(void* const* d_in, const int* in_sizes, int n_in,
                              void* d_out, int out_size) {
    const float* nodes = (const float*)d_in[0];
    const float* edges = (const float*)d_in[1];
    const float* W_emb = (const float*)d_in[2];
    const float* b_emb = (const float*)d_in[3];
    const float* Wf0   = (const float*)d_in[4];
    const float* w1_0  = (const float*)d_in[5];
    const float* b1_0  = (const float*)d_in[6];
    const float* w2_0  = (const float*)d_in[7];
    const float* b2_0  = (const float*)d_in[8];
    const float* bias0 = (const float*)d_in[9];
    const float* Wf1   = (const float*)d_in[10];
    const float* w1_1  = (const float*)d_in[11];
    const float* b1_1  = (const float*)d_in[12];
    const float* w2_1  = (const float*)d_in[13];
    const float* b2_1  = (const float*)d_in[14];
    const float* bias1 = (const float*)d_in[15];
    const float* W_out = (const float*)d_in[16];
    const float* b_out = (const float*)d_in[17];
    float* out = (float*)d_out;

    const int COMB_BLOCKS = (CC * NN * 64) / 4 / 256;   // 2048

    k_split_edges<<<BNN / 4 / 256, 256>>>((const float4*)edges);
    k_embed<<<(BB * NN) / 4, 256>>>(nodes, W_emb, b_emb);

    // ---- layer 0 (DIN = 64) ----
    k_wh<64><<<dim3(NN / 64, BB, EH), 128>>>(Wf0, w1_0, b1_0, w2_0, b2_0);
    k_stats<<<dim3(2, 64, 8), 256>>>();
    k_whnT<<<dim3(NN / 64, CC), 256>>>();
    k_msg_mma<<<dim3(NN / 128, 8, 2), 256>>>();
    k_comb<0><<<COMB_BLOCKS, 256>>>(bias0);

    // ---- layer 1 (DIN = 256) ----
    k_wh<256><<<dim3(NN / 64, BB, EH), 128>>>(Wf1, w1_1, b1_1, w2_1, b2_1);
    k_stats<<<dim3(2, 64, 8), 256>>>();
    k_whnT<<<dim3(NN / 64, CC), 256>>>();
    k_msg_mma<<<dim3(NN / 128, 8, 2), 256>>>();
    k_comb<1><<<COMB_BLOCKS, 256>>>(bias1);

    // ---- final reduction + output head ----
    k_reduce1<<<dim3(16, BB), 256>>>();
    k_out<<<1, 256>>>(W_out, b_out, out);
}